// round 10
// baseline (speedup 1.0000x reference)
#include <cuda_runtime.h>
#include <cuda_bf16.h>
#include <cstdint>

// ---------------------------------------------------------------------------
// Attention via legacy warp-MMA (mma.sync bf16) with fused split epilogues.
//   O = softmax((X Wq)(X Wk)^T / 32) (X Wv),  B=4 S=2048 D=DQKV=1024, fp32 I/O.
//
// GEMM: D[m,n] = sum_k A[m,k]*B[n,k]  (both K-major), split-bf16 3-term
// (AhBh + AhBl + AlBh) with fp32 accumulators -> ~2e-5 rel err.
//
// R9->R10: warp grid 2x4 (64x32 tiles) -> 2x2 (64x64 tiles), 128 threads.
// Cuts per-chunk ldmatrix smem traffic 96KB -> 64KB (the measured bottleneck).
// ---------------------------------------------------------------------------

static const int Bv = 4, Sv = 2048, Dv = 1024, DQ = 1024;
static const int MS = Bv * Sv; // 8192

#define TILE 128
#define KCH 32
#define KPAD 40
#define GEMM_THREADS 128
#define BUFB (128 * KPAD * 2)     // 10240 B per operand buffer
#define STAGEB (4 * BUFB)
#define DSMEMB (2 * STAGEB)       // 81920 B (also covers 128x133 fp32 epi tile)

// ------------------------------- scratch -----------------------------------
__device__ __align__(16) __nv_bfloat16 g_Xh[(size_t)MS * Dv];
__device__ __align__(16) __nv_bfloat16 g_Xl[(size_t)MS * Dv];
__device__ __align__(16) __nv_bfloat16 g_Wqh[(size_t)Dv * DQ];
__device__ __align__(16) __nv_bfloat16 g_Wql[(size_t)Dv * DQ];
__device__ __align__(16) __nv_bfloat16 g_Wkh[(size_t)Dv * DQ];
__device__ __align__(16) __nv_bfloat16 g_Wkl[(size_t)Dv * DQ];
__device__ __align__(16) __nv_bfloat16 g_Wvh[(size_t)Dv * DQ];
__device__ __align__(16) __nv_bfloat16 g_Wvl[(size_t)Dv * DQ];
__device__ __align__(16) __nv_bfloat16 g_Qh[(size_t)MS * DQ];
__device__ __align__(16) __nv_bfloat16 g_Ql[(size_t)MS * DQ];
__device__ __align__(16) __nv_bfloat16 g_Kh[(size_t)MS * DQ];
__device__ __align__(16) __nv_bfloat16 g_Kl[(size_t)MS * DQ];
__device__ __align__(16) __nv_bfloat16 g_Vth[(size_t)MS * DQ];
__device__ __align__(16) __nv_bfloat16 g_Vtl[(size_t)MS * DQ];
__device__ __align__(16) float g_S[(size_t)Bv * Sv * Sv];
__device__ __align__(16) __nv_bfloat16 g_Ph[(size_t)Bv * Sv * Sv];
__device__ __align__(16) __nv_bfloat16 g_Pl[(size_t)Bv * Sv * Sv];

// ------------------------------ PTX helpers --------------------------------
__device__ __forceinline__ uint32_t smem_u32(const void* p) {
    uint32_t a;
    asm("{ .reg .u64 t; cvta.to.shared.u64 t, %1; cvt.u32.u64 %0, t; }" : "=r"(a) : "l"(p));
    return a;
}
__device__ __forceinline__ void cp16(uint32_t dst, const void* src) {
    asm volatile("cp.async.cg.shared.global [%0], [%1], 16;" :: "r"(dst), "l"(src) : "memory");
}
__device__ __forceinline__ void ldsm4(uint32_t* r, uint32_t addr) {
    asm volatile("ldmatrix.sync.aligned.m8n8.x4.shared.b16 {%0,%1,%2,%3}, [%4];"
                 : "=r"(r[0]), "=r"(r[1]), "=r"(r[2]), "=r"(r[3]) : "r"(addr));
}
__device__ __forceinline__ void mma16816(float* d, const uint32_t* a, uint32_t b0, uint32_t b1) {
    asm volatile(
        "mma.sync.aligned.m16n8k16.row.col.f32.bf16.bf16.f32 "
        "{%0,%1,%2,%3}, {%4,%5,%6,%7}, {%8,%9}, {%0,%1,%2,%3};"
        : "+f"(d[0]), "+f"(d[1]), "+f"(d[2]), "+f"(d[3])
        : "r"(a[0]), "r"(a[1]), "r"(a[2]), "r"(a[3]), "r"(b0), "r"(b1));
}
__device__ __forceinline__ void split1(float v, __nv_bfloat16& h, __nv_bfloat16& l) {
    h = __float2bfloat16_rn(v);
    l = __float2bfloat16_rn(v - __bfloat162float(h));
}

// ------------------------------ GEMM kernel --------------------------------
// grid = (N/128, M/128, batch), block = 128 (4 warps, 64x64 warp tiles).
// EPI: 0 -> Cf fp32 [M,N]; 1 -> Ch/Cl bf16 [M,N]; 2 -> Ch/Cl bf16 [N,Sv]
//      per batch (transposed; used with z=1, M=B*Sv).
template <int EPI>
__global__ __launch_bounds__(GEMM_THREADS)
void gemm_mma(const __nv_bfloat16* __restrict__ Ah, const __nv_bfloat16* __restrict__ Al,
              const __nv_bfloat16* __restrict__ Bh, const __nv_bfloat16* __restrict__ Bl,
              float* __restrict__ Cf, __nv_bfloat16* __restrict__ Ch,
              __nv_bfloat16* __restrict__ Cl, int Nn, int K, float alpha,
              size_t sA, size_t sB, size_t sC)
{
    extern __shared__ char dsm[];
    const int tid = threadIdx.x;
    const int lane = tid & 31, wid = tid >> 5;

    const size_t aOff = (size_t)blockIdx.z * sA + (size_t)(blockIdx.y * TILE) * K;
    const size_t bOff = (size_t)blockIdx.z * sB + (size_t)(blockIdx.x * TILE) * K;
    const __nv_bfloat16* bases[4] = { Ah + aOff, Al + aOff, Bh + bOff, Bl + bOff };

    const uint32_t s0 = smem_u32(dsm);
    const int wm = wid & 1, wn = wid >> 1;        // 2x2 warp grid
    const int m0 = wm * 64, n0 = wn * 64;

    float acc[4][8][4];
#pragma unroll
    for (int i = 0; i < 4; i++)
#pragma unroll
        for (int j = 0; j < 8; j++)
#pragma unroll
            for (int q = 0; q < 4; q++) acc[i][j][q] = 0.0f;

    auto load_stage = [&](int s, int kt) {
        const uint32_t base = s0 + (uint32_t)s * STAGEB;
#pragma unroll
        for (int i = 0; i < 16; i++) {
            const int buf = i >> 2;
            const int idx = ((i & 3) << 7) + tid;     // 0..511
            const int r = idx >> 2, c = idx & 3;
            cp16(base + (uint32_t)buf * BUFB + (uint32_t)(r * KPAD + c * 8) * 2,
                 bases[buf] + (size_t)r * K + kt + c * 8);
        }
        asm volatile("cp.async.commit_group;" ::: "memory");
    };

    const int nCh = K / KCH;
    load_stage(0, 0);

    for (int c = 0; c < nCh; ++c) {
        if (c + 1 < nCh) {
            load_stage((c + 1) & 1, (c + 1) * KCH);
            asm volatile("cp.async.wait_group 1;" ::: "memory");
        } else {
            asm volatile("cp.async.wait_group 0;" ::: "memory");
        }
        __syncthreads();

        const uint32_t stg = s0 + (uint32_t)(c & 1) * STAGEB;
        const uint32_t sAh = stg + 0 * BUFB, sAl = stg + 1 * BUFB;
        const uint32_t sBh = stg + 2 * BUFB, sBl = stg + 3 * BUFB;

#pragma unroll
        for (int ks = 0; ks < 2; ks++) {
            const int k0 = ks * 16;
            uint32_t ah[4][4], al[4][4];
#pragma unroll
            for (int mt = 0; mt < 4; mt++) {
                const uint32_t off =
                    (uint32_t)((m0 + mt * 16 + (lane & 15)) * KPAD + k0 + (lane >> 4) * 8) * 2;
                ldsm4(ah[mt], sAh + off);
                ldsm4(al[mt], sAl + off);
            }
            uint32_t bh[4][4], bl[4][4];
#pragma unroll
            for (int p = 0; p < 4; p++) {
                const uint32_t off =
                    (uint32_t)((n0 + p * 16 + (lane & 15)) * KPAD + k0 + (lane >> 4) * 8) * 2;
                ldsm4(bh[p], sBh + off);
                ldsm4(bl[p], sBl + off);
            }
#pragma unroll
            for (int mt = 0; mt < 4; mt++)
#pragma unroll
                for (int nt = 0; nt < 8; nt++) {
                    const int p = nt >> 1, q = nt & 1;
                    mma16816(acc[mt][nt], ah[mt], bh[p][q], bh[p][q + 2]);
                    mma16816(acc[mt][nt], ah[mt], bl[p][q], bl[p][q + 2]);
                    mma16816(acc[mt][nt], al[mt], bh[p][q], bh[p][q + 2]);
                }
        }
        __syncthreads();
    }

    const int mGrp = lane >> 2, nGrp = (lane & 3) * 2;

    if (EPI == 0) {
        float* C = Cf + (size_t)blockIdx.z * sC;
#pragma unroll
        for (int mt = 0; mt < 4; mt++) {
            const int m = blockIdx.y * TILE + m0 + mt * 16 + mGrp;
#pragma unroll
            for (int nt = 0; nt < 8; nt++) {
                const int n = blockIdx.x * TILE + n0 + nt * 8 + nGrp;
                float2 v0 = { acc[mt][nt][0] * alpha, acc[mt][nt][1] * alpha };
                float2 v1 = { acc[mt][nt][2] * alpha, acc[mt][nt][3] * alpha };
                *reinterpret_cast<float2*>(&C[(size_t)m * Nn + n]) = v0;
                *reinterpret_cast<float2*>(&C[(size_t)(m + 8) * Nn + n]) = v1;
            }
        }
    } else if (EPI == 1) {
#pragma unroll
        for (int mt = 0; mt < 4; mt++) {
            const int m = blockIdx.y * TILE + m0 + mt * 16 + mGrp;
#pragma unroll
            for (int nt = 0; nt < 8; nt++) {
                const int n = blockIdx.x * TILE + n0 + nt * 8 + nGrp;
#pragma unroll
                for (int half = 0; half < 2; half++) {
                    const size_t o = (size_t)(m + half * 8) * Nn + n;
                    __nv_bfloat16 h0, h1, l0, l1;
                    split1(acc[mt][nt][half * 2 + 0], h0, l0);
                    split1(acc[mt][nt][half * 2 + 1], h1, l1);
                    __nv_bfloat162 hh; hh.x = h0; hh.y = h1;
                    __nv_bfloat162 ll; ll.x = l0; ll.y = l1;
                    *reinterpret_cast<__nv_bfloat162*>(Ch + o) = hh;
                    *reinterpret_cast<__nv_bfloat162*>(Cl + o) = ll;
                }
            }
        }
    } else {
        // EPI == 2: smem transpose stage, then split hi/lo to [N, Sv] per batch
        float* ep = reinterpret_cast<float*>(dsm);   // 128 x 133 fp32 tile
#pragma unroll
        for (int mt = 0; mt < 4; mt++) {
            const int ml = m0 + mt * 16 + mGrp;
#pragma unroll
            for (int nt = 0; nt < 8; nt++) {
                const int nl = n0 + nt * 8 + nGrp;
#pragma unroll
                for (int half = 0; half < 2; half++) {
                    ep[(ml + half * 8) * 133 + nl]     = acc[mt][nt][half * 2 + 0];
                    ep[(ml + half * 8) * 133 + nl + 1] = acc[mt][nt][half * 2 + 1];
                }
            }
        }
        __syncthreads();
        const int mG0 = blockIdx.y * TILE;
        const int b = mG0 / Sv;
        const int sRow = mG0 % Sv;
        __nv_bfloat16* oh = Ch + (size_t)b * Sv * DQ;
        __nv_bfloat16* ol = Cl + (size_t)b * Sv * DQ;
#pragma unroll
        for (int j = 0; j < 128; j++) {
            const int flat = j * 128 + tid;
            const int n = flat >> 7, m = flat & 127;   // lanes vary m -> coalesced
            __nv_bfloat16 h, l;
            split1(ep[m * 133 + n], h, l);
            const size_t o = (size_t)(blockIdx.x * TILE + n) * Sv + sRow + m;
            oh[o] = h; ol[o] = l;
        }
    }
}

// ------------------------- elementwise split kernels -----------------------
__global__ __launch_bounds__(256)
void split_kernel(const float* __restrict__ in, __nv_bfloat16* __restrict__ hi,
                  __nv_bfloat16* __restrict__ lo, size_t n)
{
    size_t i = ((size_t)blockIdx.x * 256 + threadIdx.x) * 4;
    if (i >= n) return;
    float4 v = *reinterpret_cast<const float4*>(in + i);
    __nv_bfloat16 h0, h1, h2, h3, l0, l1, l2, l3;
    split1(v.x, h0, l0); split1(v.y, h1, l1); split1(v.z, h2, l2); split1(v.w, h3, l3);
    __nv_bfloat162* ph = reinterpret_cast<__nv_bfloat162*>(hi + i);
    __nv_bfloat162* pl = reinterpret_cast<__nv_bfloat162*>(lo + i);
    __nv_bfloat162 a; a.x = h0; a.y = h1; ph[0] = a;
    __nv_bfloat162 b; b.x = h2; b.y = h3; ph[1] = b;
    __nv_bfloat162 c; c.x = l0; c.y = l1; pl[0] = c;
    __nv_bfloat162 d; d.x = l2; d.y = l3; pl[1] = d;
}

__global__ __launch_bounds__(256)
void splitT_kernel(const float* __restrict__ in, __nv_bfloat16* __restrict__ hi,
                   __nv_bfloat16* __restrict__ lo, int R, int C)
{
    __shared__ float t[32][33];
    const int tx = threadIdx.x, ty = threadIdx.y;
    const int x0 = blockIdx.x * 32, y0 = blockIdx.y * 32;
#pragma unroll
    for (int j = ty; j < 32; j += 8)
        t[j][tx] = in[(size_t)(y0 + j) * C + x0 + tx];
    __syncthreads();
#pragma unroll
    for (int j = ty; j < 32; j += 8) {
        float v = t[tx][j];
        __nv_bfloat16 h, l;
        split1(v, h, l);
        const size_t o = (size_t)(x0 + j) * R + y0 + tx;
        hi[o] = h; lo[o] = l;
    }
}

// ------------------------------- softmax -----------------------------------
__global__ __launch_bounds__(256)
void softmax_split_kernel(const float* __restrict__ S, __nv_bfloat16* __restrict__ Ph,
                          __nv_bfloat16* __restrict__ Pl)
{
    const float4* row = reinterpret_cast<const float4*>(S + (size_t)blockIdx.x * Sv);
    __nv_bfloat162* ph = reinterpret_cast<__nv_bfloat162*>(Ph + (size_t)blockIdx.x * Sv);
    __nv_bfloat162* pl = reinterpret_cast<__nv_bfloat162*>(Pl + (size_t)blockIdx.x * Sv);
    const int tid = threadIdx.x, lane = tid & 31, warp = tid >> 5;
    __shared__ float red[8];

    float4 v0 = row[tid];
    float4 v1 = row[tid + 256];

    float m = fmaxf(fmaxf(fmaxf(v0.x, v0.y), fmaxf(v0.z, v0.w)),
                    fmaxf(fmaxf(v1.x, v1.y), fmaxf(v1.z, v1.w)));
#pragma unroll
    for (int o = 16; o > 0; o >>= 1) m = fmaxf(m, __shfl_xor_sync(~0u, m, o));
    if (lane == 0) red[warp] = m;
    __syncthreads();
    m = red[0];
#pragma unroll
    for (int w = 1; w < 8; w++) m = fmaxf(m, red[w]);

    v0.x = __expf(v0.x - m); v0.y = __expf(v0.y - m);
    v0.z = __expf(v0.z - m); v0.w = __expf(v0.w - m);
    v1.x = __expf(v1.x - m); v1.y = __expf(v1.y - m);
    v1.z = __expf(v1.z - m); v1.w = __expf(v1.w - m);

    float s = (v0.x + v0.y) + (v0.z + v0.w) + (v1.x + v1.y) + (v1.z + v1.w);
#pragma unroll
    for (int o = 16; o > 0; o >>= 1) s += __shfl_xor_sync(~0u, s, o);
    __syncthreads();
    if (lane == 0) red[warp] = s;
    __syncthreads();
    s = red[0];
#pragma unroll
    for (int w = 1; w < 8; w++) s += red[w];
    const float inv = 1.0f / s;

    __nv_bfloat16 h0, h1, l0, l1;
    __nv_bfloat162 hh, ll;
    split1(v0.x * inv, h0, l0); split1(v0.y * inv, h1, l1);
    hh.x = h0; hh.y = h1; ll.x = l0; ll.y = l1;
    ph[tid * 2] = hh; pl[tid * 2] = ll;
    split1(v0.z * inv, h0, l0); split1(v0.w * inv, h1, l1);
    hh.x = h0; hh.y = h1; ll.x = l0; ll.y = l1;
    ph[tid * 2 + 1] = hh; pl[tid * 2 + 1] = ll;
    split1(v1.x * inv, h0, l0); split1(v1.y * inv, h1, l1);
    hh.x = h0; hh.y = h1; ll.x = l0; ll.y = l1;
    ph[tid * 2 + 512] = hh; pl[tid * 2 + 512] = ll;
    split1(v1.z * inv, h0, l0); split1(v1.w * inv, h1, l1);
    hh.x = h0; hh.y = h1; ll.x = l0; ll.y = l1;
    ph[tid * 2 + 513] = hh; pl[tid * 2 + 513] = ll;
}

// ------------------------------- launcher ----------------------------------
extern "C" void kernel_launch(void* const* d_in, const int* in_sizes, int n_in,
                              void* d_out, int out_size)
{
    const float* x  = (const float*)d_in[0];
    const float* wq = (const float*)d_in[1];
    const float* wk = (const float*)d_in[2];
    const float* wv = (const float*)d_in[3];
    float* out = (float*)d_out;

    static int smem_set = 0;
    if (!smem_set) {
        cudaFuncSetAttribute(gemm_mma<0>, cudaFuncAttributeMaxDynamicSharedMemorySize, DSMEMB);
        cudaFuncSetAttribute(gemm_mma<1>, cudaFuncAttributeMaxDynamicSharedMemorySize, DSMEMB);
        cudaFuncSetAttribute(gemm_mma<2>, cudaFuncAttributeMaxDynamicSharedMemorySize, DSMEMB);
        smem_set = 1;
    }

    __nv_bfloat16 *Xh, *Xl, *Wqh, *Wql, *Wkh, *Wkl, *Wvh, *Wvl;
    __nv_bfloat16 *Qh, *Ql, *Kh, *Kl, *Vth, *Vtl, *Ph, *Pl;
    float *S;
    cudaGetSymbolAddress((void**)&Xh, g_Xh);   cudaGetSymbolAddress((void**)&Xl, g_Xl);
    cudaGetSymbolAddress((void**)&Wqh, g_Wqh); cudaGetSymbolAddress((void**)&Wql, g_Wql);
    cudaGetSymbolAddress((void**)&Wkh, g_Wkh); cudaGetSymbolAddress((void**)&Wkl, g_Wkl);
    cudaGetSymbolAddress((void**)&Wvh, g_Wvh); cudaGetSymbolAddress((void**)&Wvl, g_Wvl);
    cudaGetSymbolAddress((void**)&S, g_S);
    cudaGetSymbolAddress((void**)&Qh, g_Qh);   cudaGetSymbolAddress((void**)&Ql, g_Ql);
    cudaGetSymbolAddress((void**)&Kh, g_Kh);   cudaGetSymbolAddress((void**)&Kl, g_Kl);
    cudaGetSymbolAddress((void**)&Vth, g_Vth); cudaGetSymbolAddress((void**)&Vtl, g_Vtl);
    cudaGetSymbolAddress((void**)&Ph, g_Ph);   cudaGetSymbolAddress((void**)&Pl, g_Pl);

    const size_t nX = (size_t)MS * Dv;

    // 1) split X; transpose+split weights (W^T -> [N,K] K-major)
    split_kernel<<<(unsigned)(nX / 1024), 256>>>(x, Xh, Xl, nX);
    {
        dim3 b(32, 8), g(DQ / 32, Dv / 32, 1);
        splitT_kernel<<<g, b>>>(wq, Wqh, Wql, Dv, DQ);
        splitT_kernel<<<g, b>>>(wk, Wkh, Wkl, Dv, DQ);
        splitT_kernel<<<g, b>>>(wv, Wvh, Wvl, Dv, DQ);
    }

    // 2) QKV projections with fused split epilogues
    {
        dim3 grid(DQ / TILE, MS / TILE, 1);
        gemm_mma<1><<<grid, GEMM_THREADS, DSMEMB>>>(
            Xh, Xl, Wqh, Wql, nullptr, Qh, Ql, DQ, Dv, 1.0f, 0, 0, 0);
        gemm_mma<1><<<grid, GEMM_THREADS, DSMEMB>>>(
            Xh, Xl, Wkh, Wkl, nullptr, Kh, Kl, DQ, Dv, 1.0f, 0, 0, 0);
        gemm_mma<2><<<grid, GEMM_THREADS, DSMEMB>>>(
            Xh, Xl, Wvh, Wvl, nullptr, Vth, Vtl, DQ, Dv, 1.0f, 0, 0, 0);
    }

    // 3) scores S = Q K^T / 32 (batched)
    {
        dim3 grid(Sv / TILE, Sv / TILE, Bv);
        gemm_mma<0><<<grid, GEMM_THREADS, DSMEMB>>>(
            Qh, Ql, Kh, Kl, S, nullptr, nullptr, Sv, DQ, 0.03125f,
            (size_t)Sv * DQ, (size_t)Sv * DQ, (size_t)Sv * Sv);
    }

    // 4) softmax -> P (bf16 hi/lo), register-resident rows
    softmax_split_kernel<<<Bv * Sv, 256>>>(S, Ph, Pl);

    // 5) O = P V  (P:[S,S], V^T:[DQ,S] K-major)
    {
        dim3 grid(DQ / TILE, Sv / TILE, Bv);
        gemm_mma<0><<<grid, GEMM_THREADS, DSMEMB>>>(
            Ph, Pl, Vth, Vtl, out, nullptr, nullptr, DQ, Sv, 1.0f,
            (size_t)Sv * Sv, (size_t)DQ * Sv, (size_t)Sv * DQ);
    }
}

// round 11
// speedup vs baseline: 1.4079x; 1.4079x over previous
#include <cuda_runtime.h>
#include <cuda_bf16.h>
#include <cstdint>

// ---------------------------------------------------------------------------
// Attention via legacy warp-MMA (mma.sync bf16) with fused split epilogues.
//   O = softmax((X Wq)(X Wk)^T / 32) (X Wv),  B=4 S=2048 D=DQKV=1024, fp32 I/O.
//
// GEMM: D[m,n] = sum_k A[m,k]*B[n,k]  (both K-major), split-bf16 3-term
// (AhBh + AhBl + AlBh) with fp32 accumulators -> ~2e-5 rel err.
//
// R10 post-mortem: 64x64 warp tiles spilled registers (2077us). Reverted to
// R9's 8-warp 64x32 layout; this round deepens cp.async pipeline 2 -> 3 stages.
// ---------------------------------------------------------------------------

static const int Bv = 4, Sv = 2048, Dv = 1024, DQ = 1024;
static const int MS = Bv * Sv; // 8192

#define TILE 128
#define KCH 32
#define KPAD 40
#define GEMM_THREADS 256
#define BUFB (128 * KPAD * 2)     // 10240 B per operand buffer
#define STAGEB (4 * BUFB)         // 40960 B
#define NSTAGE 3
#define DSMEMB (NSTAGE * STAGEB)  // 122880 B (also covers 128x133 fp32 epi tile)

// ------------------------------- scratch -----------------------------------
__device__ __align__(16) __nv_bfloat16 g_Xh[(size_t)MS * Dv];
__device__ __align__(16) __nv_bfloat16 g_Xl[(size_t)MS * Dv];
__device__ __align__(16) __nv_bfloat16 g_Wqh[(size_t)Dv * DQ];
__device__ __align__(16) __nv_bfloat16 g_Wql[(size_t)Dv * DQ];
__device__ __align__(16) __nv_bfloat16 g_Wkh[(size_t)Dv * DQ];
__device__ __align__(16) __nv_bfloat16 g_Wkl[(size_t)Dv * DQ];
__device__ __align__(16) __nv_bfloat16 g_Wvh[(size_t)Dv * DQ];
__device__ __align__(16) __nv_bfloat16 g_Wvl[(size_t)Dv * DQ];
__device__ __align__(16) __nv_bfloat16 g_Qh[(size_t)MS * DQ];
__device__ __align__(16) __nv_bfloat16 g_Ql[(size_t)MS * DQ];
__device__ __align__(16) __nv_bfloat16 g_Kh[(size_t)MS * DQ];
__device__ __align__(16) __nv_bfloat16 g_Kl[(size_t)MS * DQ];
__device__ __align__(16) __nv_bfloat16 g_Vth[(size_t)MS * DQ];
__device__ __align__(16) __nv_bfloat16 g_Vtl[(size_t)MS * DQ];
__device__ __align__(16) float g_S[(size_t)Bv * Sv * Sv];
__device__ __align__(16) __nv_bfloat16 g_Ph[(size_t)Bv * Sv * Sv];
__device__ __align__(16) __nv_bfloat16 g_Pl[(size_t)Bv * Sv * Sv];

// ------------------------------ PTX helpers --------------------------------
__device__ __forceinline__ uint32_t smem_u32(const void* p) {
    uint32_t a;
    asm("{ .reg .u64 t; cvta.to.shared.u64 t, %1; cvt.u32.u64 %0, t; }" : "=r"(a) : "l"(p));
    return a;
}
__device__ __forceinline__ void cp16(uint32_t dst, const void* src) {
    asm volatile("cp.async.cg.shared.global [%0], [%1], 16;" :: "r"(dst), "l"(src) : "memory");
}
__device__ __forceinline__ void ldsm4(uint32_t* r, uint32_t addr) {
    asm volatile("ldmatrix.sync.aligned.m8n8.x4.shared.b16 {%0,%1,%2,%3}, [%4];"
                 : "=r"(r[0]), "=r"(r[1]), "=r"(r[2]), "=r"(r[3]) : "r"(addr));
}
__device__ __forceinline__ void mma16816(float* d, const uint32_t* a, uint32_t b0, uint32_t b1) {
    asm volatile(
        "mma.sync.aligned.m16n8k16.row.col.f32.bf16.bf16.f32 "
        "{%0,%1,%2,%3}, {%4,%5,%6,%7}, {%8,%9}, {%0,%1,%2,%3};"
        : "+f"(d[0]), "+f"(d[1]), "+f"(d[2]), "+f"(d[3])
        : "r"(a[0]), "r"(a[1]), "r"(a[2]), "r"(a[3]), "r"(b0), "r"(b1));
}
__device__ __forceinline__ void split1(float v, __nv_bfloat16& h, __nv_bfloat16& l) {
    h = __float2bfloat16_rn(v);
    l = __float2bfloat16_rn(v - __bfloat162float(h));
}

// ------------------------------ GEMM kernel --------------------------------
// grid = (N/128, M/128, batch), block = 256 (8 warps, 64x32 warp tiles).
// EPI: 0 -> Cf fp32 [M,N]; 1 -> Ch/Cl bf16 [M,N]; 2 -> Ch/Cl bf16 [N,Sv]
//      per batch (transposed; used with z=1, M=B*Sv).
template <int EPI>
__global__ __launch_bounds__(GEMM_THREADS)
void gemm_mma(const __nv_bfloat16* __restrict__ Ah, const __nv_bfloat16* __restrict__ Al,
              const __nv_bfloat16* __restrict__ Bh, const __nv_bfloat16* __restrict__ Bl,
              float* __restrict__ Cf, __nv_bfloat16* __restrict__ Ch,
              __nv_bfloat16* __restrict__ Cl, int Nn, int K, float alpha,
              size_t sA, size_t sB, size_t sC)
{
    extern __shared__ char dsm[];
    const int tid = threadIdx.x;
    const int lane = tid & 31, wid = tid >> 5;

    const size_t aOff = (size_t)blockIdx.z * sA + (size_t)(blockIdx.y * TILE) * K;
    const size_t bOff = (size_t)blockIdx.z * sB + (size_t)(blockIdx.x * TILE) * K;
    const __nv_bfloat16* bases[4] = { Ah + aOff, Al + aOff, Bh + bOff, Bl + bOff };

    const uint32_t s0 = smem_u32(dsm);
    const int wm = wid & 1, wn = wid >> 1;       // 2x4 warp grid
    const int m0 = wm * 64, n0 = wn * 32;

    float acc[4][4][4];
#pragma unroll
    for (int i = 0; i < 4; i++)
#pragma unroll
        for (int j = 0; j < 4; j++)
#pragma unroll
            for (int q = 0; q < 4; q++) acc[i][j][q] = 0.0f;

    auto load_stage = [&](int s, int kt) {
        const uint32_t base = s0 + (uint32_t)s * STAGEB;
#pragma unroll
        for (int i = 0; i < 8; i++) {
            const int buf = i >> 1;
            const int idx = ((i & 1) << 8) + tid;
            const int r = idx >> 2, c = idx & 3;
            cp16(base + (uint32_t)buf * BUFB + (uint32_t)(r * KPAD + c * 8) * 2,
                 bases[buf] + (size_t)r * K + kt + c * 8);
        }
        asm volatile("cp.async.commit_group;" ::: "memory");
    };

    const int nCh = K / KCH;
    load_stage(0, 0);
    load_stage(1, KCH);

    int stage = 0;
    for (int c = 0; c < nCh; ++c) {
        if (c + 2 < nCh) {
            int s2 = stage + 2; if (s2 >= NSTAGE) s2 -= NSTAGE;
            load_stage(s2, (c + 2) * KCH);
            asm volatile("cp.async.wait_group 2;" ::: "memory");
        } else if (c + 1 < nCh) {
            asm volatile("cp.async.wait_group 1;" ::: "memory");
        } else {
            asm volatile("cp.async.wait_group 0;" ::: "memory");
        }
        __syncthreads();

        const uint32_t stg = s0 + (uint32_t)stage * STAGEB;
        const uint32_t sAh = stg + 0 * BUFB, sAl = stg + 1 * BUFB;
        const uint32_t sBh = stg + 2 * BUFB, sBl = stg + 3 * BUFB;

#pragma unroll
        for (int ks = 0; ks < 2; ks++) {
            const int k0 = ks * 16;
            uint32_t ah[4][4], al[4][4];
#pragma unroll
            for (int mt = 0; mt < 4; mt++) {
                const uint32_t off =
                    (uint32_t)((m0 + mt * 16 + (lane & 15)) * KPAD + k0 + (lane >> 4) * 8) * 2;
                ldsm4(ah[mt], sAh + off);
                ldsm4(al[mt], sAl + off);
            }
            uint32_t bh[2][4], bl[2][4];
#pragma unroll
            for (int p = 0; p < 2; p++) {
                const uint32_t off =
                    (uint32_t)((n0 + p * 16 + (lane & 15)) * KPAD + k0 + (lane >> 4) * 8) * 2;
                ldsm4(bh[p], sBh + off);
                ldsm4(bl[p], sBl + off);
            }
#pragma unroll
            for (int mt = 0; mt < 4; mt++)
#pragma unroll
                for (int nt = 0; nt < 4; nt++) {
                    const int p = nt >> 1, q = nt & 1;
                    mma16816(acc[mt][nt], ah[mt], bh[p][q], bh[p][q + 2]);
                    mma16816(acc[mt][nt], ah[mt], bl[p][q], bl[p][q + 2]);
                    mma16816(acc[mt][nt], al[mt], bh[p][q], bh[p][q + 2]);
                }
        }
        __syncthreads();
        if (++stage == NSTAGE) stage = 0;
    }

    const int mGrp = lane >> 2, nGrp = (lane & 3) * 2;

    if (EPI == 0) {
        float* C = Cf + (size_t)blockIdx.z * sC;
#pragma unroll
        for (int mt = 0; mt < 4; mt++) {
            const int m = blockIdx.y * TILE + m0 + mt * 16 + mGrp;
#pragma unroll
            for (int nt = 0; nt < 4; nt++) {
                const int n = blockIdx.x * TILE + n0 + nt * 8 + nGrp;
                float2 v0 = { acc[mt][nt][0] * alpha, acc[mt][nt][1] * alpha };
                float2 v1 = { acc[mt][nt][2] * alpha, acc[mt][nt][3] * alpha };
                *reinterpret_cast<float2*>(&C[(size_t)m * Nn + n]) = v0;
                *reinterpret_cast<float2*>(&C[(size_t)(m + 8) * Nn + n]) = v1;
            }
        }
    } else if (EPI == 1) {
#pragma unroll
        for (int mt = 0; mt < 4; mt++) {
            const int m = blockIdx.y * TILE + m0 + mt * 16 + mGrp;
#pragma unroll
            for (int nt = 0; nt < 4; nt++) {
                const int n = blockIdx.x * TILE + n0 + nt * 8 + nGrp;
#pragma unroll
                for (int half = 0; half < 2; half++) {
                    const size_t o = (size_t)(m + half * 8) * Nn + n;
                    __nv_bfloat16 h0, h1, l0, l1;
                    split1(acc[mt][nt][half * 2 + 0], h0, l0);
                    split1(acc[mt][nt][half * 2 + 1], h1, l1);
                    __nv_bfloat162 hh; hh.x = h0; hh.y = h1;
                    __nv_bfloat162 ll; ll.x = l0; ll.y = l1;
                    *reinterpret_cast<__nv_bfloat162*>(Ch + o) = hh;
                    *reinterpret_cast<__nv_bfloat162*>(Cl + o) = ll;
                }
            }
        }
    } else {
        // EPI == 2: smem transpose stage, then split hi/lo to [N, Sv] per batch
        float* ep = reinterpret_cast<float*>(dsm);   // 128 x 133 fp32 tile
#pragma unroll
        for (int mt = 0; mt < 4; mt++) {
            const int ml = m0 + mt * 16 + mGrp;
#pragma unroll
            for (int nt = 0; nt < 4; nt++) {
                const int nl = n0 + nt * 8 + nGrp;
#pragma unroll
                for (int half = 0; half < 2; half++) {
                    ep[(ml + half * 8) * 133 + nl]     = acc[mt][nt][half * 2 + 0];
                    ep[(ml + half * 8) * 133 + nl + 1] = acc[mt][nt][half * 2 + 1];
                }
            }
        }
        __syncthreads();
        const int mG0 = blockIdx.y * TILE;
        const int b = mG0 / Sv;
        const int sRow = mG0 % Sv;
        __nv_bfloat16* oh = Ch + (size_t)b * Sv * DQ;
        __nv_bfloat16* ol = Cl + (size_t)b * Sv * DQ;
#pragma unroll
        for (int j = 0; j < 64; j++) {
            const int flat = j * 256 + tid;
            const int n = flat >> 7, m = flat & 127;   // lanes vary m -> coalesced
            __nv_bfloat16 h, l;
            split1(ep[m * 133 + n], h, l);
            const size_t o = (size_t)(blockIdx.x * TILE + n) * Sv + sRow + m;
            oh[o] = h; ol[o] = l;
        }
    }
}

// ------------------------- elementwise split kernels -----------------------
__global__ __launch_bounds__(256)
void split_kernel(const float* __restrict__ in, __nv_bfloat16* __restrict__ hi,
                  __nv_bfloat16* __restrict__ lo, size_t n)
{
    size_t i = ((size_t)blockIdx.x * 256 + threadIdx.x) * 4;
    if (i >= n) return;
    float4 v = *reinterpret_cast<const float4*>(in + i);
    __nv_bfloat16 h0, h1, h2, h3, l0, l1, l2, l3;
    split1(v.x, h0, l0); split1(v.y, h1, l1); split1(v.z, h2, l2); split1(v.w, h3, l3);
    __nv_bfloat162* ph = reinterpret_cast<__nv_bfloat162*>(hi + i);
    __nv_bfloat162* pl = reinterpret_cast<__nv_bfloat162*>(lo + i);
    __nv_bfloat162 a; a.x = h0; a.y = h1; ph[0] = a;
    __nv_bfloat162 b; b.x = h2; b.y = h3; ph[1] = b;
    __nv_bfloat162 c; c.x = l0; c.y = l1; pl[0] = c;
    __nv_bfloat162 d; d.x = l2; d.y = l3; pl[1] = d;
}

__global__ __launch_bounds__(256)
void splitT_kernel(const float* __restrict__ in, __nv_bfloat16* __restrict__ hi,
                   __nv_bfloat16* __restrict__ lo, int R, int C)
{
    __shared__ float t[32][33];
    const int tx = threadIdx.x, ty = threadIdx.y;
    const int x0 = blockIdx.x * 32, y0 = blockIdx.y * 32;
#pragma unroll
    for (int j = ty; j < 32; j += 8)
        t[j][tx] = in[(size_t)(y0 + j) * C + x0 + tx];
    __syncthreads();
#pragma unroll
    for (int j = ty; j < 32; j += 8) {
        float v = t[tx][j];
        __nv_bfloat16 h, l;
        split1(v, h, l);
        const size_t o = (size_t)(x0 + j) * R + y0 + tx;
        hi[o] = h; lo[o] = l;
    }
}

// ------------------------------- softmax -----------------------------------
__global__ __launch_bounds__(256)
void softmax_split_kernel(const float* __restrict__ S, __nv_bfloat16* __restrict__ Ph,
                          __nv_bfloat16* __restrict__ Pl)
{
    const float4* row = reinterpret_cast<const float4*>(S + (size_t)blockIdx.x * Sv);
    __nv_bfloat162* ph = reinterpret_cast<__nv_bfloat162*>(Ph + (size_t)blockIdx.x * Sv);
    __nv_bfloat162* pl = reinterpret_cast<__nv_bfloat162*>(Pl + (size_t)blockIdx.x * Sv);
    const int tid = threadIdx.x, lane = tid & 31, warp = tid >> 5;
    __shared__ float red[8];

    float4 v0 = row[tid];
    float4 v1 = row[tid + 256];

    float m = fmaxf(fmaxf(fmaxf(v0.x, v0.y), fmaxf(v0.z, v0.w)),
                    fmaxf(fmaxf(v1.x, v1.y), fmaxf(v1.z, v1.w)));
#pragma unroll
    for (int o = 16; o > 0; o >>= 1) m = fmaxf(m, __shfl_xor_sync(~0u, m, o));
    if (lane == 0) red[warp] = m;
    __syncthreads();
    m = red[0];
#pragma unroll
    for (int w = 1; w < 8; w++) m = fmaxf(m, red[w]);

    v0.x = __expf(v0.x - m); v0.y = __expf(v0.y - m);
    v0.z = __expf(v0.z - m); v0.w = __expf(v0.w - m);
    v1.x = __expf(v1.x - m); v1.y = __expf(v1.y - m);
    v1.z = __expf(v1.z - m); v1.w = __expf(v1.w - m);

    float s = (v0.x + v0.y) + (v0.z + v0.w) + (v1.x + v1.y) + (v1.z + v1.w);
#pragma unroll
    for (int o = 16; o > 0; o >>= 1) s += __shfl_xor_sync(~0u, s, o);
    __syncthreads();
    if (lane == 0) red[warp] = s;
    __syncthreads();
    s = red[0];
#pragma unroll
    for (int w = 1; w < 8; w++) s += red[w];
    const float inv = 1.0f / s;

    __nv_bfloat16 h0, h1, l0, l1;
    __nv_bfloat162 hh, ll;
    split1(v0.x * inv, h0, l0); split1(v0.y * inv, h1, l1);
    hh.x = h0; hh.y = h1; ll.x = l0; ll.y = l1;
    ph[tid * 2] = hh; pl[tid * 2] = ll;
    split1(v0.z * inv, h0, l0); split1(v0.w * inv, h1, l1);
    hh.x = h0; hh.y = h1; ll.x = l0; ll.y = l1;
    ph[tid * 2 + 1] = hh; pl[tid * 2 + 1] = ll;
    split1(v1.x * inv, h0, l0); split1(v1.y * inv, h1, l1);
    hh.x = h0; hh.y = h1; ll.x = l0; ll.y = l1;
    ph[tid * 2 + 512] = hh; pl[tid * 2 + 512] = ll;
    split1(v1.z * inv, h0, l0); split1(v1.w * inv, h1, l1);
    hh.x = h0; hh.y = h1; ll.x = l0; ll.y = l1;
    ph[tid * 2 + 513] = hh; pl[tid * 2 + 513] = ll;
}

// ------------------------------- launcher ----------------------------------
extern "C" void kernel_launch(void* const* d_in, const int* in_sizes, int n_in,
                              void* d_out, int out_size)
{
    const float* x  = (const float*)d_in[0];
    const float* wq = (const float*)d_in[1];
    const float* wk = (const float*)d_in[2];
    const float* wv = (const float*)d_in[3];
    float* out = (float*)d_out;

    static int smem_set = 0;
    if (!smem_set) {
        cudaFuncSetAttribute(gemm_mma<0>, cudaFuncAttributeMaxDynamicSharedMemorySize, DSMEMB);
        cudaFuncSetAttribute(gemm_mma<1>, cudaFuncAttributeMaxDynamicSharedMemorySize, DSMEMB);
        cudaFuncSetAttribute(gemm_mma<2>, cudaFuncAttributeMaxDynamicSharedMemorySize, DSMEMB);
        smem_set = 1;
    }

    __nv_bfloat16 *Xh, *Xl, *Wqh, *Wql, *Wkh, *Wkl, *Wvh, *Wvl;
    __nv_bfloat16 *Qh, *Ql, *Kh, *Kl, *Vth, *Vtl, *Ph, *Pl;
    float *S;
    cudaGetSymbolAddress((void**)&Xh, g_Xh);   cudaGetSymbolAddress((void**)&Xl, g_Xl);
    cudaGetSymbolAddress((void**)&Wqh, g_Wqh); cudaGetSymbolAddress((void**)&Wql, g_Wql);
    cudaGetSymbolAddress((void**)&Wkh, g_Wkh); cudaGetSymbolAddress((void**)&Wkl, g_Wkl);
    cudaGetSymbolAddress((void**)&Wvh, g_Wvh); cudaGetSymbolAddress((void**)&Wvl, g_Wvl);
    cudaGetSymbolAddress((void**)&S, g_S);
    cudaGetSymbolAddress((void**)&Qh, g_Qh);   cudaGetSymbolAddress((void**)&Ql, g_Ql);
    cudaGetSymbolAddress((void**)&Kh, g_Kh);   cudaGetSymbolAddress((void**)&Kl, g_Kl);
    cudaGetSymbolAddress((void**)&Vth, g_Vth); cudaGetSymbolAddress((void**)&Vtl, g_Vtl);
    cudaGetSymbolAddress((void**)&Ph, g_Ph);   cudaGetSymbolAddress((void**)&Pl, g_Pl);

    const size_t nX = (size_t)MS * Dv;

    // 1) split X; transpose+split weights (W^T -> [N,K] K-major)
    split_kernel<<<(unsigned)(nX / 1024), 256>>>(x, Xh, Xl, nX);
    {
        dim3 b(32, 8), g(DQ / 32, Dv / 32, 1);
        splitT_kernel<<<g, b>>>(wq, Wqh, Wql, Dv, DQ);
        splitT_kernel<<<g, b>>>(wk, Wkh, Wkl, Dv, DQ);
        splitT_kernel<<<g, b>>>(wv, Wvh, Wvl, Dv, DQ);
    }

    // 2) QKV projections with fused split epilogues
    {
        dim3 grid(DQ / TILE, MS / TILE, 1);
        gemm_mma<1><<<grid, GEMM_THREADS, DSMEMB>>>(
            Xh, Xl, Wqh, Wql, nullptr, Qh, Ql, DQ, Dv, 1.0f, 0, 0, 0);
        gemm_mma<1><<<grid, GEMM_THREADS, DSMEMB>>>(
            Xh, Xl, Wkh, Wkl, nullptr, Kh, Kl, DQ, Dv, 1.0f, 0, 0, 0);
        gemm_mma<2><<<grid, GEMM_THREADS, DSMEMB>>>(
            Xh, Xl, Wvh, Wvl, nullptr, Vth, Vtl, DQ, Dv, 1.0f, 0, 0, 0);
    }

    // 3) scores S = Q K^T / 32 (batched)
    {
        dim3 grid(Sv / TILE, Sv / TILE, Bv);
        gemm_mma<0><<<grid, GEMM_THREADS, DSMEMB>>>(
            Qh, Ql, Kh, Kl, S, nullptr, nullptr, Sv, DQ, 0.03125f,
            (size_t)Sv * DQ, (size_t)Sv * DQ, (size_t)Sv * Sv);
    }

    // 4) softmax -> P (bf16 hi/lo), register-resident rows
    softmax_split_kernel<<<Bv * Sv, 256>>>(S, Ph, Pl);

    // 5) O = P V  (P:[S,S], V^T:[DQ,S] K-major)
    {
        dim3 grid(DQ / TILE, Sv / TILE, Bv);
        gemm_mma<0><<<grid, GEMM_THREADS, DSMEMB>>>(
            Ph, Pl, Vth, Vtl, out, nullptr, nullptr, DQ, Sv, 1.0f,
            (size_t)Sv * Sv, (size_t)DQ * Sv, (size_t)Sv * DQ);
    }
}

// round 13
// speedup vs baseline: 1.5355x; 1.0906x over previous
#include <cuda_runtime.h>
#include <cuda_bf16.h>
#include <cstdint>

// ---------------------------------------------------------------------------
// Attention via legacy warp-MMA (mma.sync bf16) with fused split epilogues.
//   O = softmax((X Wq)(X Wk)^T / 32) (X Wv),  B=4 S=2048 D=DQKV=1024, fp32 I/O.
//
// GEMM: D[m,n] = sum_k A[m,k]*B[n,k]  (both K-major), split-bf16 3-term
// (AhBh + AhBl + AlBh) with fp32 accumulators -> ~2e-5 rel err.
//
// R11 post-mortem: 3-stage pipeline (120KB smem) regressed. Back to R9's
// 2-stage / 256-thread / 64x32-warp-tile config; this round adds intra-chunk
// fragment double-buffering (ldsm for both ks-steps issued before the MMAs)
// to overlap smem loads with tensor work.
// ---------------------------------------------------------------------------

static const int Bv = 4, Sv = 2048, Dv = 1024, DQ = 1024;
static const int MS = Bv * Sv; // 8192

#define TILE 128
#define KCH 32
#define KPAD 40
#define GEMM_THREADS 256
#define BUFB (128 * KPAD * 2)     // 10240 B per operand buffer
#define STAGEB (4 * BUFB)         // 40960 B
#define DSMEMB (2 * STAGEB)       // 81920 B (also covers 128x133 fp32 epi tile)

// ------------------------------- scratch -----------------------------------
__device__ __align__(16) __nv_bfloat16 g_Xh[(size_t)MS * Dv];
__device__ __align__(16) __nv_bfloat16 g_Xl[(size_t)MS * Dv];
__device__ __align__(16) __nv_bfloat16 g_Wqh[(size_t)Dv * DQ];
__device__ __align__(16) __nv_bfloat16 g_Wql[(size_t)Dv * DQ];
__device__ __align__(16) __nv_bfloat16 g_Wkh[(size_t)Dv * DQ];
__device__ __align__(16) __nv_bfloat16 g_Wkl[(size_t)Dv * DQ];
__device__ __align__(16) __nv_bfloat16 g_Wvh[(size_t)Dv * DQ];
__device__ __align__(16) __nv_bfloat16 g_Wvl[(size_t)Dv * DQ];
__device__ __align__(16) __nv_bfloat16 g_Qh[(size_t)MS * DQ];
__device__ __align__(16) __nv_bfloat16 g_Ql[(size_t)MS * DQ];
__device__ __align__(16) __nv_bfloat16 g_Kh[(size_t)MS * DQ];
__device__ __align__(16) __nv_bfloat16 g_Kl[(size_t)MS * DQ];
__device__ __align__(16) __nv_bfloat16 g_Vth[(size_t)MS * DQ];
__device__ __align__(16) __nv_bfloat16 g_Vtl[(size_t)MS * DQ];
__device__ __align__(16) float g_S[(size_t)Bv * Sv * Sv];
__device__ __align__(16) __nv_bfloat16 g_Ph[(size_t)Bv * Sv * Sv];
__device__ __align__(16) __nv_bfloat16 g_Pl[(size_t)Bv * Sv * Sv];

// ------------------------------ PTX helpers --------------------------------
__device__ __forceinline__ uint32_t smem_u32(const void* p) {
    uint32_t a;
    asm("{ .reg .u64 t; cvta.to.shared.u64 t, %1; cvt.u32.u64 %0, t; }" : "=r"(a) : "l"(p));
    return a;
}
__device__ __forceinline__ void cp16(uint32_t dst, const void* src) {
    asm volatile("cp.async.cg.shared.global [%0], [%1], 16;" :: "r"(dst), "l"(src) : "memory");
}
__device__ __forceinline__ void ldsm4(uint32_t* r, uint32_t addr) {
    asm volatile("ldmatrix.sync.aligned.m8n8.x4.shared.b16 {%0,%1,%2,%3}, [%4];"
                 : "=r"(r[0]), "=r"(r[1]), "=r"(r[2]), "=r"(r[3]) : "r"(addr));
}
__device__ __forceinline__ void mma16816(float* d, const uint32_t* a, uint32_t b0, uint32_t b1) {
    asm volatile(
        "mma.sync.aligned.m16n8k16.row.col.f32.bf16.bf16.f32 "
        "{%0,%1,%2,%3}, {%4,%5,%6,%7}, {%8,%9}, {%0,%1,%2,%3};"
        : "+f"(d[0]), "+f"(d[1]), "+f"(d[2]), "+f"(d[3])
        : "r"(a[0]), "r"(a[1]), "r"(a[2]), "r"(a[3]), "r"(b0), "r"(b1));
}
__device__ __forceinline__ void split1(float v, __nv_bfloat16& h, __nv_bfloat16& l) {
    h = __float2bfloat16_rn(v);
    l = __float2bfloat16_rn(v - __bfloat162float(h));
}

// ------------------------------ GEMM kernel --------------------------------
// grid = (N/128, M/128, batch), block = 256 (8 warps, 64x32 warp tiles).
// EPI: 0 -> Cf fp32 [M,N]; 1 -> Ch/Cl bf16 [M,N]; 2 -> Ch/Cl bf16 [N,Sv]
//      per batch (transposed; used with z=1, M=B*Sv).
template <int EPI>
__global__ __launch_bounds__(GEMM_THREADS, 1)
void gemm_mma(const __nv_bfloat16* __restrict__ Ah, const __nv_bfloat16* __restrict__ Al,
              const __nv_bfloat16* __restrict__ Bh, const __nv_bfloat16* __restrict__ Bl,
              float* __restrict__ Cf, __nv_bfloat16* __restrict__ Ch,
              __nv_bfloat16* __restrict__ Cl, int Nn, int K, float alpha,
              size_t sA, size_t sB, size_t sC)
{
    extern __shared__ char dsm[];
    const int tid = threadIdx.x;
    const int lane = tid & 31, wid = tid >> 5;

    const size_t aOff = (size_t)blockIdx.z * sA + (size_t)(blockIdx.y * TILE) * K;
    const size_t bOff = (size_t)blockIdx.z * sB + (size_t)(blockIdx.x * TILE) * K;
    const __nv_bfloat16* bases[4] = { Ah + aOff, Al + aOff, Bh + bOff, Bl + bOff };

    const uint32_t s0 = smem_u32(dsm);
    const int wm = wid & 1, wn = wid >> 1;       // 2x4 warp grid
    const int m0 = wm * 64, n0 = wn * 32;

    float acc[4][4][4];
#pragma unroll
    for (int i = 0; i < 4; i++)
#pragma unroll
        for (int j = 0; j < 4; j++)
#pragma unroll
            for (int q = 0; q < 4; q++) acc[i][j][q] = 0.0f;

    auto load_stage = [&](int s, int kt) {
        const uint32_t base = s0 + (uint32_t)s * STAGEB;
#pragma unroll
        for (int i = 0; i < 8; i++) {
            const int buf = i >> 1;
            const int idx = ((i & 1) << 8) + tid;
            const int r = idx >> 2, c = idx & 3;
            cp16(base + (uint32_t)buf * BUFB + (uint32_t)(r * KPAD + c * 8) * 2,
                 bases[buf] + (size_t)r * K + kt + c * 8);
        }
        asm volatile("cp.async.commit_group;" ::: "memory");
    };

    const int nCh = K / KCH;
    load_stage(0, 0);

    for (int c = 0; c < nCh; ++c) {
        if (c + 1 < nCh) {
            load_stage((c + 1) & 1, (c + 1) * KCH);
            asm volatile("cp.async.wait_group 1;" ::: "memory");
        } else {
            asm volatile("cp.async.wait_group 0;" ::: "memory");
        }
        __syncthreads();

        const uint32_t stg = s0 + (uint32_t)(c & 1) * STAGEB;
        const uint32_t sAh = stg + 0 * BUFB, sAl = stg + 1 * BUFB;
        const uint32_t sBh = stg + 2 * BUFB, sBl = stg + 3 * BUFB;

        // Intra-chunk fragment double-buffering: issue ldsm for BOTH ks steps,
        // then run the MMA streams — scoreboard overlaps ks=1 loads with ks=0 math.
        uint32_t ah[2][4][4], al[2][4][4], bh[2][2][4], bl[2][2][4];
#pragma unroll
        for (int ks = 0; ks < 2; ks++) {
            const int k0 = ks * 16;
#pragma unroll
            for (int mt = 0; mt < 4; mt++) {
                const uint32_t off =
                    (uint32_t)((m0 + mt * 16 + (lane & 15)) * KPAD + k0 + (lane >> 4) * 8) * 2;
                ldsm4(ah[ks][mt], sAh + off);
                ldsm4(al[ks][mt], sAl + off);
            }
#pragma unroll
            for (int p = 0; p < 2; p++) {
                const uint32_t off =
                    (uint32_t)((n0 + p * 16 + (lane & 15)) * KPAD + k0 + (lane >> 4) * 8) * 2;
                ldsm4(bh[ks][p], sBh + off);
                ldsm4(bl[ks][p], sBl + off);
            }
        }
#pragma unroll
        for (int ks = 0; ks < 2; ks++) {
#pragma unroll
            for (int mt = 0; mt < 4; mt++)
#pragma unroll
                for (int nt = 0; nt < 4; nt++) {
                    const int p = nt >> 1, q = nt & 1;
                    mma16816(acc[mt][nt], ah[ks][mt], bh[ks][p][q], bh[ks][p][q + 2]);
                    mma16816(acc[mt][nt], ah[ks][mt], bl[ks][p][q], bl[ks][p][q + 2]);
                    mma16816(acc[mt][nt], al[ks][mt], bh[ks][p][q], bh[ks][p][q + 2]);
                }
        }
        __syncthreads();
    }

    const int mGrp = lane >> 2, nGrp = (lane & 3) * 2;

    if (EPI == 0) {
        float* C = Cf + (size_t)blockIdx.z * sC;
#pragma unroll
        for (int mt = 0; mt < 4; mt++) {
            const int m = blockIdx.y * TILE + m0 + mt * 16 + mGrp;
#pragma unroll
            for (int nt = 0; nt < 4; nt++) {
                const int n = blockIdx.x * TILE + n0 + nt * 8 + nGrp;
                float2 v0 = { acc[mt][nt][0] * alpha, acc[mt][nt][1] * alpha };
                float2 v1 = { acc[mt][nt][2] * alpha, acc[mt][nt][3] * alpha };
                *reinterpret_cast<float2*>(&C[(size_t)m * Nn + n]) = v0;
                *reinterpret_cast<float2*>(&C[(size_t)(m + 8) * Nn + n]) = v1;
            }
        }
    } else if (EPI == 1) {
#pragma unroll
        for (int mt = 0; mt < 4; mt++) {
            const int m = blockIdx.y * TILE + m0 + mt * 16 + mGrp;
#pragma unroll
            for (int nt = 0; nt < 4; nt++) {
                const int n = blockIdx.x * TILE + n0 + nt * 8 + nGrp;
#pragma unroll
                for (int half = 0; half < 2; half++) {
                    const size_t o = (size_t)(m + half * 8) * Nn + n;
                    __nv_bfloat16 h0, h1, l0, l1;
                    split1(acc[mt][nt][half * 2 + 0], h0, l0);
                    split1(acc[mt][nt][half * 2 + 1], h1, l1);
                    __nv_bfloat162 hh; hh.x = h0; hh.y = h1;
                    __nv_bfloat162 ll; ll.x = l0; ll.y = l1;
                    *reinterpret_cast<__nv_bfloat162*>(Ch + o) = hh;
                    *reinterpret_cast<__nv_bfloat162*>(Cl + o) = ll;
                }
            }
        }
    } else {
        // EPI == 2: smem transpose stage, then split hi/lo to [N, Sv] per batch
        float* ep = reinterpret_cast<float*>(dsm);   // 128 x 133 fp32 tile
#pragma unroll
        for (int mt = 0; mt < 4; mt++) {
            const int ml = m0 + mt * 16 + mGrp;
#pragma unroll
            for (int nt = 0; nt < 4; nt++) {
                const int nl = n0 + nt * 8 + nGrp;
#pragma unroll
                for (int half = 0; half < 2; half++) {
                    ep[(ml + half * 8) * 133 + nl]     = acc[mt][nt][half * 2 + 0];
                    ep[(ml + half * 8) * 133 + nl + 1] = acc[mt][nt][half * 2 + 1];
                }
            }
        }
        __syncthreads();
        const int mG0 = blockIdx.y * TILE;
        const int b = mG0 / Sv;
        const int sRow = mG0 % Sv;
        __nv_bfloat16* oh = Ch + (size_t)b * Sv * DQ;
        __nv_bfloat16* ol = Cl + (size_t)b * Sv * DQ;
#pragma unroll
        for (int j = 0; j < 64; j++) {
            const int flat = j * 256 + tid;
            const int n = flat >> 7, m = flat & 127;   // lanes vary m -> coalesced
            __nv_bfloat16 h, l;
            split1(ep[m * 133 + n], h, l);
            const size_t o = (size_t)(blockIdx.x * TILE + n) * Sv + sRow + m;
            oh[o] = h; ol[o] = l;
        }
    }
}

// ------------------------- elementwise split kernels -----------------------
__global__ __launch_bounds__(256)
void split_kernel(const float* __restrict__ in, __nv_bfloat16* __restrict__ hi,
                  __nv_bfloat16* __restrict__ lo, size_t n)
{
    size_t i = ((size_t)blockIdx.x * 256 + threadIdx.x) * 4;
    if (i >= n) return;
    float4 v = *reinterpret_cast<const float4*>(in + i);
    __nv_bfloat16 h0, h1, h2, h3, l0, l1, l2, l3;
    split1(v.x, h0, l0); split1(v.y, h1, l1); split1(v.z, h2, l2); split1(v.w, h3, l3);
    __nv_bfloat162* ph = reinterpret_cast<__nv_bfloat162*>(hi + i);
    __nv_bfloat162* pl = reinterpret_cast<__nv_bfloat162*>(lo + i);
    __nv_bfloat162 a; a.x = h0; a.y = h1; ph[0] = a;
    __nv_bfloat162 b; b.x = h2; b.y = h3; ph[1] = b;
    __nv_bfloat162 c; c.x = l0; c.y = l1; pl[0] = c;
    __nv_bfloat162 d; d.x = l2; d.y = l3; pl[1] = d;
}

__global__ __launch_bounds__(256)
void splitT_kernel(const float* __restrict__ in, __nv_bfloat16* __restrict__ hi,
                   __nv_bfloat16* __restrict__ lo, int R, int C)
{
    __shared__ float t[32][33];
    const int tx = threadIdx.x, ty = threadIdx.y;
    const int x0 = blockIdx.x * 32, y0 = blockIdx.y * 32;
#pragma unroll
    for (int j = ty; j < 32; j += 8)
        t[j][tx] = in[(size_t)(y0 + j) * C + x0 + tx];
    __syncthreads();
#pragma unroll
    for (int j = ty; j < 32; j += 8) {
        float v = t[tx][j];
        __nv_bfloat16 h, l;
        split1(v, h, l);
        const size_t o = (size_t)(x0 + j) * R + y0 + tx;
        hi[o] = h; lo[o] = l;
    }
}

// ------------------------------- softmax -----------------------------------
__global__ __launch_bounds__(256)
void softmax_split_kernel(const float* __restrict__ S, __nv_bfloat16* __restrict__ Ph,
                          __nv_bfloat16* __restrict__ Pl)
{
    const float4* row = reinterpret_cast<const float4*>(S + (size_t)blockIdx.x * Sv);
    __nv_bfloat162* ph = reinterpret_cast<__nv_bfloat162*>(Ph + (size_t)blockIdx.x * Sv);
    __nv_bfloat162* pl = reinterpret_cast<__nv_bfloat162*>(Pl + (size_t)blockIdx.x * Sv);
    const int tid = threadIdx.x, lane = tid & 31, warp = tid >> 5;
    __shared__ float red[8];

    float4 v0 = row[tid];
    float4 v1 = row[tid + 256];

    float m = fmaxf(fmaxf(fmaxf(v0.x, v0.y), fmaxf(v0.z, v0.w)),
                    fmaxf(fmaxf(v1.x, v1.y), fmaxf(v1.z, v1.w)));
#pragma unroll
    for (int o = 16; o > 0; o >>= 1) m = fmaxf(m, __shfl_xor_sync(~0u, m, o));
    if (lane == 0) red[warp] = m;
    __syncthreads();
    m = red[0];
#pragma unroll
    for (int w = 1; w < 8; w++) m = fmaxf(m, red[w]);

    v0.x = __expf(v0.x - m); v0.y = __expf(v0.y - m);
    v0.z = __expf(v0.z - m); v0.w = __expf(v0.w - m);
    v1.x = __expf(v1.x - m); v1.y = __expf(v1.y - m);
    v1.z = __expf(v1.z - m); v1.w = __expf(v1.w - m);

    float s = (v0.x + v0.y) + (v0.z + v0.w) + (v1.x + v1.y) + (v1.z + v1.w);
#pragma unroll
    for (int o = 16; o > 0; o >>= 1) s += __shfl_xor_sync(~0u, s, o);
    __syncthreads();
    if (lane == 0) red[warp] = s;
    __syncthreads();
    s = red[0];
#pragma unroll
    for (int w = 1; w < 8; w++) s += red[w];
    const float inv = 1.0f / s;

    __nv_bfloat16 h0, h1, l0, l1;
    __nv_bfloat162 hh, ll;
    split1(v0.x * inv, h0, l0); split1(v0.y * inv, h1, l1);
    hh.x = h0; hh.y = h1; ll.x = l0; ll.y = l1;
    ph[tid * 2] = hh; pl[tid * 2] = ll;
    split1(v0.z * inv, h0, l0); split1(v0.w * inv, h1, l1);
    hh.x = h0; hh.y = h1; ll.x = l0; ll.y = l1;
    ph[tid * 2 + 1] = hh; pl[tid * 2 + 1] = ll;
    split1(v1.x * inv, h0, l0); split1(v1.y * inv, h1, l1);
    hh.x = h0; hh.y = h1; ll.x = l0; ll.y = l1;
    ph[tid * 2 + 512] = hh; pl[tid * 2 + 512] = ll;
    split1(v1.z * inv, h0, l0); split1(v1.w * inv, h1, l1);
    hh.x = h0; hh.y = h1; ll.x = l0; ll.y = l1;
    ph[tid * 2 + 513] = hh; pl[tid * 2 + 513] = ll;
}

// ------------------------------- launcher ----------------------------------
extern "C" void kernel_launch(void* const* d_in, const int* in_sizes, int n_in,
                              void* d_out, int out_size)
{
    const float* x  = (const float*)d_in[0];
    const float* wq = (const float*)d_in[1];
    const float* wk = (const float*)d_in[2];
    const float* wv = (const float*)d_in[3];
    float* out = (float*)d_out;

    static int smem_set = 0;
    if (!smem_set) {
        cudaFuncSetAttribute(gemm_mma<0>, cudaFuncAttributeMaxDynamicSharedMemorySize, DSMEMB);
        cudaFuncSetAttribute(gemm_mma<1>, cudaFuncAttributeMaxDynamicSharedMemorySize, DSMEMB);
        cudaFuncSetAttribute(gemm_mma<2>, cudaFuncAttributeMaxDynamicSharedMemorySize, DSMEMB);
        smem_set = 1;
    }

    __nv_bfloat16 *Xh, *Xl, *Wqh, *Wql, *Wkh, *Wkl, *Wvh, *Wvl;
    __nv_bfloat16 *Qh, *Ql, *Kh, *Kl, *Vth, *Vtl, *Ph, *Pl;
    float *S;
    cudaGetSymbolAddress((void**)&Xh, g_Xh);   cudaGetSymbolAddress((void**)&Xl, g_Xl);
    cudaGetSymbolAddress((void**)&Wqh, g_Wqh); cudaGetSymbolAddress((void**)&Wql, g_Wql);
    cudaGetSymbolAddress((void**)&Wkh, g_Wkh); cudaGetSymbolAddress((void**)&Wkl, g_Wkl);
    cudaGetSymbolAddress((void**)&Wvh, g_Wvh); cudaGetSymbolAddress((void**)&Wvl, g_Wvl);
    cudaGetSymbolAddress((void**)&S, g_S);
    cudaGetSymbolAddress((void**)&Qh, g_Qh);   cudaGetSymbolAddress((void**)&Ql, g_Ql);
    cudaGetSymbolAddress((void**)&Kh, g_Kh);   cudaGetSymbolAddress((void**)&Kl, g_Kl);
    cudaGetSymbolAddress((void**)&Vth, g_Vth); cudaGetSymbolAddress((void**)&Vtl, g_Vtl);
    cudaGetSymbolAddress((void**)&Ph, g_Ph);   cudaGetSymbolAddress((void**)&Pl, g_Pl);

    const size_t nX = (size_t)MS * Dv;

    // 1) split X; transpose+split weights (W^T -> [N,K] K-major)
    split_kernel<<<(unsigned)(nX / 1024), 256>>>(x, Xh, Xl, nX);
    {
        dim3 b(32, 8), g(DQ / 32, Dv / 32, 1);
        splitT_kernel<<<g, b>>>(wq, Wqh, Wql, Dv, DQ);
        splitT_kernel<<<g, b>>>(wk, Wkh, Wkl, Dv, DQ);
        splitT_kernel<<<g, b>>>(wv, Wvh, Wvl, Dv, DQ);
    }

    // 2) QKV projections with fused split epilogues
    {
        dim3 grid(DQ / TILE, MS / TILE, 1);
        gemm_mma<1><<<grid, GEMM_THREADS, DSMEMB>>>(
            Xh, Xl, Wqh, Wql, nullptr, Qh, Ql, DQ, Dv, 1.0f, 0, 0, 0);
        gemm_mma<1><<<grid, GEMM_THREADS, DSMEMB>>>(
            Xh, Xl, Wkh, Wkl, nullptr, Kh, Kl, DQ, Dv, 1.0f, 0, 0, 0);
        gemm_mma<2><<<grid, GEMM_THREADS, DSMEMB>>>(
            Xh, Xl, Wvh, Wvl, nullptr, Vth, Vtl, DQ, Dv, 1.0f, 0, 0, 0);
    }

    // 3) scores S = Q K^T / 32 (batched)
    {
        dim3 grid(Sv / TILE, Sv / TILE, Bv);
        gemm_mma<0><<<grid, GEMM_THREADS, DSMEMB>>>(
            Qh, Ql, Kh, Kl, S, nullptr, nullptr, Sv, DQ, 0.03125f,
            (size_t)Sv * DQ, (size_t)Sv * DQ, (size_t)Sv * Sv);
    }

    // 4) softmax -> P (bf16 hi/lo), register-resident rows
    softmax_split_kernel<<<Bv * Sv, 256>>>(S, Ph, Pl);

    // 5) O = P V  (P:[S,S], V^T:[DQ,S] K-major)
    {
        dim3 grid(DQ / TILE, Sv / TILE, Bv);
        gemm_mma<0><<<grid, GEMM_THREADS, DSMEMB>>>(
            Ph, Pl, Vth, Vtl, out, nullptr, nullptr, DQ, Sv, 1.0f,
            (size_t)Sv * Sv, (size_t)DQ * Sv, (size_t)Sv * DQ);
    }
}

// round 15
// speedup vs baseline: 1.9878x; 1.2946x over previous
#include <cuda_runtime.h>
#include <cuda_bf16.h>
#include <cstdint>

// ---------------------------------------------------------------------------
// Attention, mixed precision:
//   QKV projections: split-bf16 3-term warp-MMA (accurate, ~1e-5) emitting
//                    tf32-rounded fp32 Q, K, V^T.
//   scores QK^T and PV: single-pass tf32 m16n8k8 warp-MMA (~4e-4).
//   O = softmax((X Wq)(X Wk)^T / 32) (X Wv),  B=4 S=2048 D=DQKV=1024, fp32.
// ---------------------------------------------------------------------------

static const int Bv = 4, Sv = 2048, Dv = 1024, DQ = 1024;
static const int MS = Bv * Sv; // 8192

// ---- bf16 split GEMM config (QKV projections) ----
#define TILE 128
#define KCH 32
#define KPAD 40
#define GEMM_THREADS 256
#define BUFB (128 * KPAD * 2)     // 10240 B per operand buffer
#define STAGEB (4 * BUFB)         // 40960 B
#define DSMEMB (2 * STAGEB)       // 81920 B (covers 128x133 fp32 epi tile)

// ---- tf32 GEMM config (scores, PV) ----
#define KPADF 36                   // padded K-stride in floats (144 B, conflict-free)
#define BUFBF (128 * KPADF * 4)    // 18432 B per operand buffer
#define STAGEBF (2 * BUFBF)        // 36864 B (A + B)
#define DSMEMBF (2 * STAGEBF)      // 73728 B

// ------------------------------- scratch -----------------------------------
__device__ __align__(16) __nv_bfloat16 g_Xh[(size_t)MS * Dv];
__device__ __align__(16) __nv_bfloat16 g_Xl[(size_t)MS * Dv];
__device__ __align__(16) __nv_bfloat16 g_Wqh[(size_t)Dv * DQ];
__device__ __align__(16) __nv_bfloat16 g_Wql[(size_t)Dv * DQ];
__device__ __align__(16) __nv_bfloat16 g_Wkh[(size_t)Dv * DQ];
__device__ __align__(16) __nv_bfloat16 g_Wkl[(size_t)Dv * DQ];
__device__ __align__(16) __nv_bfloat16 g_Wvh[(size_t)Dv * DQ];
__device__ __align__(16) __nv_bfloat16 g_Wvl[(size_t)Dv * DQ];
__device__ __align__(16) float g_Qt[(size_t)MS * DQ];   // tf32-rounded
__device__ __align__(16) float g_Kt[(size_t)MS * DQ];   // tf32-rounded
__device__ __align__(16) float g_Vt[(size_t)MS * DQ];   // V^T, tf32-rounded
__device__ __align__(16) float g_S [(size_t)Bv * Sv * Sv];
__device__ __align__(16) float g_Pt[(size_t)Bv * Sv * Sv]; // tf32-rounded

// ------------------------------ PTX helpers --------------------------------
__device__ __forceinline__ uint32_t smem_u32(const void* p) {
    uint32_t a;
    asm("{ .reg .u64 t; cvta.to.shared.u64 t, %1; cvt.u32.u64 %0, t; }" : "=r"(a) : "l"(p));
    return a;
}
__device__ __forceinline__ void cp16(uint32_t dst, const void* src) {
    asm volatile("cp.async.cg.shared.global [%0], [%1], 16;" :: "r"(dst), "l"(src) : "memory");
}
__device__ __forceinline__ void ldsm4(uint32_t* r, uint32_t addr) {
    asm volatile("ldmatrix.sync.aligned.m8n8.x4.shared.b16 {%0,%1,%2,%3}, [%4];"
                 : "=r"(r[0]), "=r"(r[1]), "=r"(r[2]), "=r"(r[3]) : "r"(addr));
}
__device__ __forceinline__ void mma16816(float* d, const uint32_t* a, uint32_t b0, uint32_t b1) {
    asm volatile(
        "mma.sync.aligned.m16n8k16.row.col.f32.bf16.bf16.f32 "
        "{%0,%1,%2,%3}, {%4,%5,%6,%7}, {%8,%9}, {%0,%1,%2,%3};"
        : "+f"(d[0]), "+f"(d[1]), "+f"(d[2]), "+f"(d[3])
        : "r"(a[0]), "r"(a[1]), "r"(a[2]), "r"(a[3]), "r"(b0), "r"(b1));
}
__device__ __forceinline__ void mma1688_tf32(float* d, const uint32_t* a,
                                             uint32_t b0, uint32_t b1) {
    asm volatile(
        "mma.sync.aligned.m16n8k8.row.col.f32.tf32.tf32.f32 "
        "{%0,%1,%2,%3}, {%4,%5,%6,%7}, {%8,%9}, {%0,%1,%2,%3};"
        : "+f"(d[0]), "+f"(d[1]), "+f"(d[2]), "+f"(d[3])
        : "r"(a[0]), "r"(a[1]), "r"(a[2]), "r"(a[3]), "r"(b0), "r"(b1));
}
__device__ __forceinline__ uint32_t lds32(uint32_t addr) {
    uint32_t v;
    asm volatile("ld.shared.b32 %0, [%1];" : "=r"(v) : "r"(addr));
    return v;
}
__device__ __forceinline__ void split1(float v, __nv_bfloat16& h, __nv_bfloat16& l) {
    h = __float2bfloat16_rn(v);
    l = __float2bfloat16_rn(v - __bfloat162float(h));
}
__device__ __forceinline__ float tf32r(float v) {
    uint32_t o;
    asm("cvt.rna.tf32.f32 %0, %1;" : "=r"(o) : "f"(v));
    return __uint_as_float(o);
}

// --------------------- bf16 split GEMM (QKV projections) -------------------
// grid = (N/128, M/128, 1), block = 256 (8 warps, 64x32 warp tiles).
// EPI: 1 -> Cf fp32 tf32-rounded [M,N]; 2 -> Cf fp32 tf32-rounded [N,Sv]
//      per batch (transposed; M=B*Sv).
template <int EPI>
__global__ __launch_bounds__(GEMM_THREADS)
void gemm_mma(const __nv_bfloat16* __restrict__ Ah, const __nv_bfloat16* __restrict__ Al,
              const __nv_bfloat16* __restrict__ Bh, const __nv_bfloat16* __restrict__ Bl,
              float* __restrict__ Cf, int Nn, int K)
{
    extern __shared__ char dsm[];
    const int tid = threadIdx.x;
    const int lane = tid & 31, wid = tid >> 5;

    const size_t aOff = (size_t)(blockIdx.y * TILE) * K;
    const size_t bOff = (size_t)(blockIdx.x * TILE) * K;
    const __nv_bfloat16* bases[4] = { Ah + aOff, Al + aOff, Bh + bOff, Bl + bOff };

    const uint32_t s0 = smem_u32(dsm);
    const int wm = wid & 1, wn = wid >> 1;       // 2x4 warp grid
    const int m0 = wm * 64, n0 = wn * 32;

    float acc[4][4][4];
#pragma unroll
    for (int i = 0; i < 4; i++)
#pragma unroll
        for (int j = 0; j < 4; j++)
#pragma unroll
            for (int q = 0; q < 4; q++) acc[i][j][q] = 0.0f;

    auto load_stage = [&](int s, int kt) {
        const uint32_t base = s0 + (uint32_t)s * STAGEB;
#pragma unroll
        for (int i = 0; i < 8; i++) {
            const int buf = i >> 1;
            const int idx = ((i & 1) << 8) + tid;
            const int r = idx >> 2, c = idx & 3;
            cp16(base + (uint32_t)buf * BUFB + (uint32_t)(r * KPAD + c * 8) * 2,
                 bases[buf] + (size_t)r * K + kt + c * 8);
        }
        asm volatile("cp.async.commit_group;" ::: "memory");
    };

    const int nCh = K / KCH;
    load_stage(0, 0);

    for (int c = 0; c < nCh; ++c) {
        if (c + 1 < nCh) {
            load_stage((c + 1) & 1, (c + 1) * KCH);
            asm volatile("cp.async.wait_group 1;" ::: "memory");
        } else {
            asm volatile("cp.async.wait_group 0;" ::: "memory");
        }
        __syncthreads();

        const uint32_t stg = s0 + (uint32_t)(c & 1) * STAGEB;
        const uint32_t sAh = stg + 0 * BUFB, sAl = stg + 1 * BUFB;
        const uint32_t sBh = stg + 2 * BUFB, sBl = stg + 3 * BUFB;

#pragma unroll
        for (int ks = 0; ks < 2; ks++) {
            const int k0 = ks * 16;
            uint32_t ah[4][4], al[4][4];
#pragma unroll
            for (int mt = 0; mt < 4; mt++) {
                const uint32_t off =
                    (uint32_t)((m0 + mt * 16 + (lane & 15)) * KPAD + k0 + (lane >> 4) * 8) * 2;
                ldsm4(ah[mt], sAh + off);
                ldsm4(al[mt], sAl + off);
            }
            uint32_t bh[2][4], bl[2][4];
#pragma unroll
            for (int p = 0; p < 2; p++) {
                const uint32_t off =
                    (uint32_t)((n0 + p * 16 + (lane & 15)) * KPAD + k0 + (lane >> 4) * 8) * 2;
                ldsm4(bh[p], sBh + off);
                ldsm4(bl[p], sBl + off);
            }
#pragma unroll
            for (int mt = 0; mt < 4; mt++)
#pragma unroll
                for (int nt = 0; nt < 4; nt++) {
                    const int p = nt >> 1, q = nt & 1;
                    mma16816(acc[mt][nt], ah[mt], bh[p][q], bh[p][q + 2]);
                    mma16816(acc[mt][nt], ah[mt], bl[p][q], bl[p][q + 2]);
                    mma16816(acc[mt][nt], al[mt], bh[p][q], bh[p][q + 2]);
                }
        }
        __syncthreads();
    }

    const int mGrp = lane >> 2, nGrp = (lane & 3) * 2;

    if (EPI == 1) {
        // tf32-rounded fp32, [M,N]
#pragma unroll
        for (int mt = 0; mt < 4; mt++) {
            const int m = blockIdx.y * TILE + m0 + mt * 16 + mGrp;
#pragma unroll
            for (int nt = 0; nt < 4; nt++) {
                const int n = blockIdx.x * TILE + n0 + nt * 8 + nGrp;
                float2 v0 = { tf32r(acc[mt][nt][0]), tf32r(acc[mt][nt][1]) };
                float2 v1 = { tf32r(acc[mt][nt][2]), tf32r(acc[mt][nt][3]) };
                *reinterpret_cast<float2*>(&Cf[(size_t)m * Nn + n]) = v0;
                *reinterpret_cast<float2*>(&Cf[(size_t)(m + 8) * Nn + n]) = v1;
            }
        }
    } else {
        // EPI == 2: smem transpose stage, tf32-rounded to [N, Sv] per batch
        float* ep = reinterpret_cast<float*>(dsm);   // 128 x 133 fp32 tile
#pragma unroll
        for (int mt = 0; mt < 4; mt++) {
            const int ml = m0 + mt * 16 + mGrp;
#pragma unroll
            for (int nt = 0; nt < 4; nt++) {
                const int nl = n0 + nt * 8 + nGrp;
#pragma unroll
                for (int half = 0; half < 2; half++) {
                    ep[(ml + half * 8) * 133 + nl]     = acc[mt][nt][half * 2 + 0];
                    ep[(ml + half * 8) * 133 + nl + 1] = acc[mt][nt][half * 2 + 1];
                }
            }
        }
        __syncthreads();
        const int mG0 = blockIdx.y * TILE;
        const int b = mG0 / Sv;
        const int sRow = mG0 % Sv;
        float* ov = Cf + (size_t)b * Sv * DQ;
#pragma unroll
        for (int j = 0; j < 64; j++) {
            const int flat = j * 256 + tid;
            const int n = flat >> 7, m = flat & 127;   // lanes vary m -> coalesced
            const size_t o = (size_t)(blockIdx.x * TILE + n) * Sv + sRow + m;
            ov[o] = tf32r(ep[m * 133 + n]);
        }
    }
}

// ------------------------- tf32 GEMM (scores, PV) --------------------------
// D[m,n] = alpha * sum_k A[m,k]*B[n,k]; A [M,K], B [N,K], fp32 pre-rounded
// to tf32. grid = (N/128, M/128, batch), block = 256 (8 warps, 64x32 tiles).
__global__ __launch_bounds__(GEMM_THREADS)
void gemm_tf32(const float* __restrict__ A, const float* __restrict__ B,
               float* __restrict__ C, int Nn, int K, float alpha,
               size_t sA, size_t sB, size_t sC)
{
    extern __shared__ char dsm[];
    const int tid = threadIdx.x;
    const int lane = tid & 31, wid = tid >> 5;
    const int gr = lane >> 2, tg = lane & 3;

    const float* aBase = A + (size_t)blockIdx.z * sA + (size_t)(blockIdx.y * TILE) * K;
    const float* bBase = B + (size_t)blockIdx.z * sB + (size_t)(blockIdx.x * TILE) * K;

    const uint32_t s0 = smem_u32(dsm);
    const int wm = wid & 1, wn = wid >> 1;       // 2x4 warp grid
    const int m0 = wm * 64, n0 = wn * 32;

    float acc[4][4][4];
#pragma unroll
    for (int i = 0; i < 4; i++)
#pragma unroll
        for (int j = 0; j < 4; j++)
#pragma unroll
            for (int q = 0; q < 4; q++) acc[i][j][q] = 0.0f;

    auto load_stage = [&](int s, int kt) {
        const uint32_t base = s0 + (uint32_t)s * STAGEBF;
#pragma unroll
        for (int i = 0; i < 8; i++) {
            const int buf = i >> 2;                     // 0 = A, 1 = B
            const int j = ((i & 3) << 8) + tid;         // 0..1023
            const int r = j >> 3, c = j & 7;
            const float* src = (buf == 0 ? aBase : bBase) + (size_t)r * K + kt + c * 4;
            cp16(base + (uint32_t)buf * BUFBF + (uint32_t)(r * KPADF + c * 4) * 4, src);
        }
        asm volatile("cp.async.commit_group;" ::: "memory");
    };

    const int nCh = K / KCH;                      // KCH = 32 floats per chunk
    load_stage(0, 0);

    for (int c = 0; c < nCh; ++c) {
        if (c + 1 < nCh) {
            load_stage((c + 1) & 1, (c + 1) * KCH);
            asm volatile("cp.async.wait_group 1;" ::: "memory");
        } else {
            asm volatile("cp.async.wait_group 0;" ::: "memory");
        }
        __syncthreads();

        const uint32_t stg = s0 + (uint32_t)(c & 1) * STAGEBF;
        const uint32_t sAm = stg, sBm = stg + BUFBF;

#pragma unroll
        for (int ks = 0; ks < 4; ks++) {
            const int k0 = ks * 8;
            // A fragments: m16n8k8 tf32 -> 4 regs
            uint32_t a[4][4];
#pragma unroll
            for (int mt = 0; mt < 4; mt++) {
                const uint32_t r0 =
                    sAm + (uint32_t)((m0 + mt * 16 + gr) * KPADF + k0 + tg) * 4;
                a[mt][0] = lds32(r0);
                a[mt][1] = lds32(r0 + 8u * KPADF * 4u);
                a[mt][2] = lds32(r0 + 16u);
                a[mt][3] = lds32(r0 + 8u * KPADF * 4u + 16u);
            }
            // B fragments: 2 regs per n8 tile
            uint32_t b[4][2];
#pragma unroll
            for (int nt = 0; nt < 4; nt++) {
                const uint32_t r0 =
                    sBm + (uint32_t)((n0 + nt * 8 + gr) * KPADF + k0 + tg) * 4;
                b[nt][0] = lds32(r0);
                b[nt][1] = lds32(r0 + 16u);
            }
#pragma unroll
            for (int mt = 0; mt < 4; mt++)
#pragma unroll
                for (int nt = 0; nt < 4; nt++)
                    mma1688_tf32(acc[mt][nt], a[mt], b[nt][0], b[nt][1]);
        }
        __syncthreads();
    }

    // fp32 epilogue
    const int mGrp = lane >> 2, nGrp = (lane & 3) * 2;
    float* Co = C + (size_t)blockIdx.z * sC;
#pragma unroll
    for (int mt = 0; mt < 4; mt++) {
        const int m = blockIdx.y * TILE + m0 + mt * 16 + mGrp;
#pragma unroll
        for (int nt = 0; nt < 4; nt++) {
            const int n = blockIdx.x * TILE + n0 + nt * 8 + nGrp;
            float2 v0 = { acc[mt][nt][0] * alpha, acc[mt][nt][1] * alpha };
            float2 v1 = { acc[mt][nt][2] * alpha, acc[mt][nt][3] * alpha };
            *reinterpret_cast<float2*>(&Co[(size_t)m * Nn + n]) = v0;
            *reinterpret_cast<float2*>(&Co[(size_t)(m + 8) * Nn + n]) = v1;
        }
    }
}

// ------------------------- elementwise split kernels -----------------------
__global__ __launch_bounds__(256)
void split_kernel(const float* __restrict__ in, __nv_bfloat16* __restrict__ hi,
                  __nv_bfloat16* __restrict__ lo, size_t n)
{
    size_t i = ((size_t)blockIdx.x * 256 + threadIdx.x) * 4;
    if (i >= n) return;
    float4 v = *reinterpret_cast<const float4*>(in + i);
    __nv_bfloat16 h0, h1, h2, h3, l0, l1, l2, l3;
    split1(v.x, h0, l0); split1(v.y, h1, l1); split1(v.z, h2, l2); split1(v.w, h3, l3);
    __nv_bfloat162* ph = reinterpret_cast<__nv_bfloat162*>(hi + i);
    __nv_bfloat162* pl = reinterpret_cast<__nv_bfloat162*>(lo + i);
    __nv_bfloat162 a; a.x = h0; a.y = h1; ph[0] = a;
    __nv_bfloat162 b; b.x = h2; b.y = h3; ph[1] = b;
    __nv_bfloat162 c; c.x = l0; c.y = l1; pl[0] = c;
    __nv_bfloat162 d; d.x = l2; d.y = l3; pl[1] = d;
}

__global__ __launch_bounds__(256)
void splitT_kernel(const float* __restrict__ in, __nv_bfloat16* __restrict__ hi,
                   __nv_bfloat16* __restrict__ lo, int R, int C)
{
    __shared__ float t[32][33];
    const int tx = threadIdx.x, ty = threadIdx.y;
    const int x0 = blockIdx.x * 32, y0 = blockIdx.y * 32;
#pragma unroll
    for (int j = ty; j < 32; j += 8)
        t[j][tx] = in[(size_t)(y0 + j) * C + x0 + tx];
    __syncthreads();
#pragma unroll
    for (int j = ty; j < 32; j += 8) {
        float v = t[tx][j];
        __nv_bfloat16 h, l;
        split1(v, h, l);
        const size_t o = (size_t)(x0 + j) * R + y0 + tx;
        hi[o] = h; lo[o] = l;
    }
}

// ------------------------------- softmax -----------------------------------
// Row of 2048 fp32 in registers; emits tf32-rounded P.
__global__ __launch_bounds__(256)
void softmax_tf32_kernel(const float* __restrict__ S, float* __restrict__ P)
{
    const float4* row = reinterpret_cast<const float4*>(S + (size_t)blockIdx.x * Sv);
    float4* prow = reinterpret_cast<float4*>(P + (size_t)blockIdx.x * Sv);
    const int tid = threadIdx.x, lane = tid & 31, warp = tid >> 5;
    __shared__ float red[8];

    float4 v0 = row[tid];
    float4 v1 = row[tid + 256];

    float m = fmaxf(fmaxf(fmaxf(v0.x, v0.y), fmaxf(v0.z, v0.w)),
                    fmaxf(fmaxf(v1.x, v1.y), fmaxf(v1.z, v1.w)));
#pragma unroll
    for (int o = 16; o > 0; o >>= 1) m = fmaxf(m, __shfl_xor_sync(~0u, m, o));
    if (lane == 0) red[warp] = m;
    __syncthreads();
    m = red[0];
#pragma unroll
    for (int w = 1; w < 8; w++) m = fmaxf(m, red[w]);

    v0.x = __expf(v0.x - m); v0.y = __expf(v0.y - m);
    v0.z = __expf(v0.z - m); v0.w = __expf(v0.w - m);
    v1.x = __expf(v1.x - m); v1.y = __expf(v1.y - m);
    v1.z = __expf(v1.z - m); v1.w = __expf(v1.w - m);

    float s = (v0.x + v0.y) + (v0.z + v0.w) + (v1.x + v1.y) + (v1.z + v1.w);
#pragma unroll
    for (int o = 16; o > 0; o >>= 1) s += __shfl_xor_sync(~0u, s, o);
    __syncthreads();
    if (lane == 0) red[warp] = s;
    __syncthreads();
    s = red[0];
#pragma unroll
    for (int w = 1; w < 8; w++) s += red[w];
    const float inv = 1.0f / s;

    float4 r0 = { tf32r(v0.x * inv), tf32r(v0.y * inv), tf32r(v0.z * inv), tf32r(v0.w * inv) };
    float4 r1 = { tf32r(v1.x * inv), tf32r(v1.y * inv), tf32r(v1.z * inv), tf32r(v1.w * inv) };
    prow[tid] = r0;
    prow[tid + 256] = r1;
}

// ------------------------------- launcher ----------------------------------
extern "C" void kernel_launch(void* const* d_in, const int* in_sizes, int n_in,
                              void* d_out, int out_size)
{
    const float* x  = (const float*)d_in[0];
    const float* wq = (const float*)d_in[1];
    const float* wk = (const float*)d_in[2];
    const float* wv = (const float*)d_in[3];
    float* out = (float*)d_out;

    static int smem_set = 0;
    if (!smem_set) {
        cudaFuncSetAttribute(gemm_mma<1>, cudaFuncAttributeMaxDynamicSharedMemorySize, DSMEMB);
        cudaFuncSetAttribute(gemm_mma<2>, cudaFuncAttributeMaxDynamicSharedMemorySize, DSMEMB);
        cudaFuncSetAttribute(gemm_tf32, cudaFuncAttributeMaxDynamicSharedMemorySize, DSMEMBF);
        smem_set = 1;
    }

    __nv_bfloat16 *Xh, *Xl, *Wqh, *Wql, *Wkh, *Wkl, *Wvh, *Wvl;
    float *Qt, *Kt, *Vt, *S, *Pt;
    cudaGetSymbolAddress((void**)&Xh, g_Xh);   cudaGetSymbolAddress((void**)&Xl, g_Xl);
    cudaGetSymbolAddress((void**)&Wqh, g_Wqh); cudaGetSymbolAddress((void**)&Wql, g_Wql);
    cudaGetSymbolAddress((void**)&Wkh, g_Wkh); cudaGetSymbolAddress((void**)&Wkl, g_Wkl);
    cudaGetSymbolAddress((void**)&Wvh, g_Wvh); cudaGetSymbolAddress((void**)&Wvl, g_Wvl);
    cudaGetSymbolAddress((void**)&Qt, g_Qt);   cudaGetSymbolAddress((void**)&Kt, g_Kt);
    cudaGetSymbolAddress((void**)&Vt, g_Vt);   cudaGetSymbolAddress((void**)&S, g_S);
    cudaGetSymbolAddress((void**)&Pt, g_Pt);

    const size_t nX = (size_t)MS * Dv;

    // 1) split X; transpose+split weights (W^T -> [N,K] K-major)
    split_kernel<<<(unsigned)(nX / 1024), 256>>>(x, Xh, Xl, nX);
    {
        dim3 b(32, 8), g(DQ / 32, Dv / 32, 1);
        splitT_kernel<<<g, b>>>(wq, Wqh, Wql, Dv, DQ);
        splitT_kernel<<<g, b>>>(wk, Wkh, Wkl, Dv, DQ);
        splitT_kernel<<<g, b>>>(wv, Wvh, Wvl, Dv, DQ);
    }

    // 2) QKV projections (split-bf16), emit tf32-rounded fp32
    {
        dim3 grid(DQ / TILE, MS / TILE, 1);
        gemm_mma<1><<<grid, GEMM_THREADS, DSMEMB>>>(Xh, Xl, Wqh, Wql, Qt, DQ, Dv);
        gemm_mma<1><<<grid, GEMM_THREADS, DSMEMB>>>(Xh, Xl, Wkh, Wkl, Kt, DQ, Dv);
        gemm_mma<2><<<grid, GEMM_THREADS, DSMEMB>>>(Xh, Xl, Wvh, Wvl, Vt, DQ, Dv);
    }

    // 3) scores S = Q K^T / 32 (tf32, batched)
    {
        dim3 grid(Sv / TILE, Sv / TILE, Bv);
        gemm_tf32<<<grid, GEMM_THREADS, DSMEMBF>>>(
            Qt, Kt, S, Sv, DQ, 0.03125f,
            (size_t)Sv * DQ, (size_t)Sv * DQ, (size_t)Sv * Sv);
    }

    // 4) softmax -> P (tf32-rounded fp32)
    softmax_tf32_kernel<<<Bv * Sv, 256>>>(S, Pt);

    // 5) O = P V (tf32; P:[S,S], V^T:[DQ,S] K-major)
    {
        dim3 grid(DQ / TILE, Sv / TILE, Bv);
        gemm_tf32<<<grid, GEMM_THREADS, DSMEMBF>>>(
            Pt, Vt, out, DQ, Sv, 1.0f,
            (size_t)Sv * Sv, (size_t)DQ * Sv, (size_t)Sv * DQ);
    }
}

// round 16
// speedup vs baseline: 2.3901x; 1.2024x over previous
#include <cuda_runtime.h>
#include <cuda_bf16.h>
#include <cstdint>

// ---------------------------------------------------------------------------
// Attention, all-tf32 tensor path:
//   O = softmax((X Wq)(X Wk)^T / 32) (X Wv),  B=4 S=2048 D=DQKV=1024, fp32.
//
// All five GEMMs run single-pass tf32 m16n8k8 warp-MMA (fp32 accum) on
// tf32-pre-rounded (cvt.rna) operands. Measured error model from R15:
// attention-side tf32 gave 3.45e-4; projection-side accumulation adds in RSS
// -> expected ~5-6.5e-4 (budget 1e-3).
// ---------------------------------------------------------------------------

static const int Bv = 4, Sv = 2048, Dv = 1024, DQ = 1024;
static const int MS = Bv * Sv; // 8192

#define TILE 128
#define KCH 32
#define GEMM_THREADS 256
#define KPADF 36                   // padded K-stride in floats (144 B)
#define BUFBF (128 * KPADF * 4)    // 18432 B per operand buffer
#define STAGEBF (2 * BUFBF)        // 36864 B (A + B)
#define DSMEMBF (2 * STAGEBF)      // 73728 B (covers 128x133 fp32 epi tile)

// ------------------------------- scratch -----------------------------------
__device__ __align__(16) float g_Xt [(size_t)MS * Dv];     // tf32-rounded X
__device__ __align__(16) float g_Wqt[(size_t)DQ * Dv];     // W^T, tf32-rounded
__device__ __align__(16) float g_Wkt[(size_t)DQ * Dv];
__device__ __align__(16) float g_Wvt[(size_t)DQ * Dv];
__device__ __align__(16) float g_Qt [(size_t)MS * DQ];     // tf32-rounded
__device__ __align__(16) float g_Kt [(size_t)MS * DQ];
__device__ __align__(16) float g_Vt [(size_t)MS * DQ];     // V^T, tf32-rounded
__device__ __align__(16) float g_S  [(size_t)Bv * Sv * Sv];
__device__ __align__(16) float g_Pt [(size_t)Bv * Sv * Sv];

// ------------------------------ PTX helpers --------------------------------
__device__ __forceinline__ uint32_t smem_u32(const void* p) {
    uint32_t a;
    asm("{ .reg .u64 t; cvta.to.shared.u64 t, %1; cvt.u32.u64 %0, t; }" : "=r"(a) : "l"(p));
    return a;
}
__device__ __forceinline__ void cp16(uint32_t dst, const void* src) {
    asm volatile("cp.async.cg.shared.global [%0], [%1], 16;" :: "r"(dst), "l"(src) : "memory");
}
__device__ __forceinline__ void mma1688_tf32(float* d, const uint32_t* a,
                                             uint32_t b0, uint32_t b1) {
    asm volatile(
        "mma.sync.aligned.m16n8k8.row.col.f32.tf32.tf32.f32 "
        "{%0,%1,%2,%3}, {%4,%5,%6,%7}, {%8,%9}, {%0,%1,%2,%3};"
        : "+f"(d[0]), "+f"(d[1]), "+f"(d[2]), "+f"(d[3])
        : "r"(a[0]), "r"(a[1]), "r"(a[2]), "r"(a[3]), "r"(b0), "r"(b1));
}
__device__ __forceinline__ uint32_t lds32(uint32_t addr) {
    uint32_t v;
    asm volatile("ld.shared.b32 %0, [%1];" : "=r"(v) : "r"(addr));
    return v;
}
__device__ __forceinline__ float tf32r(float v) {
    uint32_t o;
    asm("cvt.rna.tf32.f32 %0, %1;" : "=r"(o) : "f"(v));
    return __uint_as_float(o);
}

// ------------------------------ tf32 GEMM ----------------------------------
// D[m,n] = alpha * sum_k A[m,k]*B[n,k]; A [M,K], B [N,K] (both K-major,
// tf32-pre-rounded fp32). grid = (N/128, M/128, batch), block = 256
// (8 warps, 64x32 warp tiles).
// EPI: 0 -> fp32*alpha [M,N]; 1 -> tf32-rounded fp32 [M,N];
//      2 -> transposed tf32-rounded fp32 [N,Sv] per batch (z=1, M=B*Sv).
template <int EPI>
__global__ __launch_bounds__(GEMM_THREADS)
void gemm_tf32(const float* __restrict__ A, const float* __restrict__ B,
               float* __restrict__ C, int Nn, int K, float alpha,
               size_t sA, size_t sB, size_t sC)
{
    extern __shared__ char dsm[];
    const int tid = threadIdx.x;
    const int lane = tid & 31, wid = tid >> 5;
    const int gr = lane >> 2, tg = lane & 3;

    const float* aBase = A + (size_t)blockIdx.z * sA + (size_t)(blockIdx.y * TILE) * K;
    const float* bBase = B + (size_t)blockIdx.z * sB + (size_t)(blockIdx.x * TILE) * K;

    const uint32_t s0 = smem_u32(dsm);
    const int wm = wid & 1, wn = wid >> 1;       // 2x4 warp grid
    const int m0 = wm * 64, n0 = wn * 32;

    float acc[4][4][4];
#pragma unroll
    for (int i = 0; i < 4; i++)
#pragma unroll
        for (int j = 0; j < 4; j++)
#pragma unroll
            for (int q = 0; q < 4; q++) acc[i][j][q] = 0.0f;

    auto load_stage = [&](int s, int kt) {
        const uint32_t base = s0 + (uint32_t)s * STAGEBF;
#pragma unroll
        for (int i = 0; i < 8; i++) {
            const int buf = i >> 2;                     // 0 = A, 1 = B
            const int j = ((i & 3) << 8) + tid;         // 0..1023
            const int r = j >> 3, c = j & 7;
            const float* src = (buf == 0 ? aBase : bBase) + (size_t)r * K + kt + c * 4;
            cp16(base + (uint32_t)buf * BUFBF + (uint32_t)(r * KPADF + c * 4) * 4, src);
        }
        asm volatile("cp.async.commit_group;" ::: "memory");
    };

    const int nCh = K / KCH;                      // 32 floats per chunk
    load_stage(0, 0);

    for (int c = 0; c < nCh; ++c) {
        if (c + 1 < nCh) {
            load_stage((c + 1) & 1, (c + 1) * KCH);
            asm volatile("cp.async.wait_group 1;" ::: "memory");
        } else {
            asm volatile("cp.async.wait_group 0;" ::: "memory");
        }
        __syncthreads();

        const uint32_t stg = s0 + (uint32_t)(c & 1) * STAGEBF;
        const uint32_t sAm = stg, sBm = stg + BUFBF;

#pragma unroll
        for (int ks = 0; ks < 4; ks++) {
            const int k0 = ks * 8;
            uint32_t a[4][4];
#pragma unroll
            for (int mt = 0; mt < 4; mt++) {
                const uint32_t r0 =
                    sAm + (uint32_t)((m0 + mt * 16 + gr) * KPADF + k0 + tg) * 4;
                a[mt][0] = lds32(r0);
                a[mt][1] = lds32(r0 + 8u * KPADF * 4u);
                a[mt][2] = lds32(r0 + 16u);
                a[mt][3] = lds32(r0 + 8u * KPADF * 4u + 16u);
            }
            uint32_t b[4][2];
#pragma unroll
            for (int nt = 0; nt < 4; nt++) {
                const uint32_t r0 =
                    sBm + (uint32_t)((n0 + nt * 8 + gr) * KPADF + k0 + tg) * 4;
                b[nt][0] = lds32(r0);
                b[nt][1] = lds32(r0 + 16u);
            }
#pragma unroll
            for (int mt = 0; mt < 4; mt++)
#pragma unroll
                for (int nt = 0; nt < 4; nt++)
                    mma1688_tf32(acc[mt][nt], a[mt], b[nt][0], b[nt][1]);
        }
        __syncthreads();
    }

    const int mGrp = lane >> 2, nGrp = (lane & 3) * 2;

    if (EPI == 0 || EPI == 1) {
        float* Co = C + (size_t)blockIdx.z * sC;
#pragma unroll
        for (int mt = 0; mt < 4; mt++) {
            const int m = blockIdx.y * TILE + m0 + mt * 16 + mGrp;
#pragma unroll
            for (int nt = 0; nt < 4; nt++) {
                const int n = blockIdx.x * TILE + n0 + nt * 8 + nGrp;
                float2 v0, v1;
                if (EPI == 0) {
                    v0 = make_float2(acc[mt][nt][0] * alpha, acc[mt][nt][1] * alpha);
                    v1 = make_float2(acc[mt][nt][2] * alpha, acc[mt][nt][3] * alpha);
                } else {
                    v0 = make_float2(tf32r(acc[mt][nt][0]), tf32r(acc[mt][nt][1]));
                    v1 = make_float2(tf32r(acc[mt][nt][2]), tf32r(acc[mt][nt][3]));
                }
                *reinterpret_cast<float2*>(&Co[(size_t)m * Nn + n]) = v0;
                *reinterpret_cast<float2*>(&Co[(size_t)(m + 8) * Nn + n]) = v1;
            }
        }
    } else {
        // EPI == 2: smem transpose stage, tf32-rounded to [N, Sv] per batch
        float* ep = reinterpret_cast<float*>(dsm);   // 128 x 133 fp32 tile
#pragma unroll
        for (int mt = 0; mt < 4; mt++) {
            const int ml = m0 + mt * 16 + mGrp;
#pragma unroll
            for (int nt = 0; nt < 4; nt++) {
                const int nl = n0 + nt * 8 + nGrp;
#pragma unroll
                for (int half = 0; half < 2; half++) {
                    ep[(ml + half * 8) * 133 + nl]     = acc[mt][nt][half * 2 + 0];
                    ep[(ml + half * 8) * 133 + nl + 1] = acc[mt][nt][half * 2 + 1];
                }
            }
        }
        __syncthreads();
        const int mG0 = blockIdx.y * TILE;
        const int b = mG0 / Sv;
        const int sRow = mG0 % Sv;
        float* ov = C + (size_t)b * Sv * DQ;
#pragma unroll
        for (int j = 0; j < 64; j++) {
            const int flat = j * 256 + tid;
            const int n = flat >> 7, m = flat & 127;   // lanes vary m -> coalesced
            const size_t o = (size_t)(blockIdx.x * TILE + n) * Sv + sRow + m;
            ov[o] = tf32r(ep[m * 133 + n]);
        }
    }
}

// ------------------------- elementwise round kernels -----------------------
__global__ __launch_bounds__(256)
void round_kernel(const float* __restrict__ in, float* __restrict__ outp, size_t n)
{
    size_t i = ((size_t)blockIdx.x * 256 + threadIdx.x) * 4;
    if (i >= n) return;
    float4 v = *reinterpret_cast<const float4*>(in + i);
    v.x = tf32r(v.x); v.y = tf32r(v.y); v.z = tf32r(v.z); v.w = tf32r(v.w);
    *reinterpret_cast<float4*>(outp + i) = v;
}

// Transpose + round: in [R,C] row-major -> out [C,R]. grid(C/32, R/32)
__global__ __launch_bounds__(256)
void roundT_kernel(const float* __restrict__ in, float* __restrict__ outp,
                   int R, int C)
{
    __shared__ float t[32][33];
    const int tx = threadIdx.x, ty = threadIdx.y;
    const int x0 = blockIdx.x * 32, y0 = blockIdx.y * 32;
#pragma unroll
    for (int j = ty; j < 32; j += 8)
        t[j][tx] = in[(size_t)(y0 + j) * C + x0 + tx];
    __syncthreads();
#pragma unroll
    for (int j = ty; j < 32; j += 8)
        outp[(size_t)(x0 + j) * R + y0 + tx] = tf32r(t[tx][j]);
}

// ------------------------------- softmax -----------------------------------
// Row of 2048 fp32 in registers; emits tf32-rounded P.
__global__ __launch_bounds__(256)
void softmax_tf32_kernel(const float* __restrict__ S, float* __restrict__ P)
{
    const float4* row = reinterpret_cast<const float4*>(S + (size_t)blockIdx.x * Sv);
    float4* prow = reinterpret_cast<float4*>(P + (size_t)blockIdx.x * Sv);
    const int tid = threadIdx.x, lane = tid & 31, warp = tid >> 5;
    __shared__ float red[8];

    float4 v0 = row[tid];
    float4 v1 = row[tid + 256];

    float m = fmaxf(fmaxf(fmaxf(v0.x, v0.y), fmaxf(v0.z, v0.w)),
                    fmaxf(fmaxf(v1.x, v1.y), fmaxf(v1.z, v1.w)));
#pragma unroll
    for (int o = 16; o > 0; o >>= 1) m = fmaxf(m, __shfl_xor_sync(~0u, m, o));
    if (lane == 0) red[warp] = m;
    __syncthreads();
    m = red[0];
#pragma unroll
    for (int w = 1; w < 8; w++) m = fmaxf(m, red[w]);

    v0.x = __expf(v0.x - m); v0.y = __expf(v0.y - m);
    v0.z = __expf(v0.z - m); v0.w = __expf(v0.w - m);
    v1.x = __expf(v1.x - m); v1.y = __expf(v1.y - m);
    v1.z = __expf(v1.z - m); v1.w = __expf(v1.w - m);

    float s = (v0.x + v0.y) + (v0.z + v0.w) + (v1.x + v1.y) + (v1.z + v1.w);
#pragma unroll
    for (int o = 16; o > 0; o >>= 1) s += __shfl_xor_sync(~0u, s, o);
    __syncthreads();
    if (lane == 0) red[warp] = s;
    __syncthreads();
    s = red[0];
#pragma unroll
    for (int w = 1; w < 8; w++) s += red[w];
    const float inv = 1.0f / s;

    float4 r0 = { tf32r(v0.x * inv), tf32r(v0.y * inv), tf32r(v0.z * inv), tf32r(v0.w * inv) };
    float4 r1 = { tf32r(v1.x * inv), tf32r(v1.y * inv), tf32r(v1.z * inv), tf32r(v1.w * inv) };
    prow[tid] = r0;
    prow[tid + 256] = r1;
}

// ------------------------------- launcher ----------------------------------
extern "C" void kernel_launch(void* const* d_in, const int* in_sizes, int n_in,
                              void* d_out, int out_size)
{
    const float* x  = (const float*)d_in[0];
    const float* wq = (const float*)d_in[1];
    const float* wk = (const float*)d_in[2];
    const float* wv = (const float*)d_in[3];
    float* out = (float*)d_out;

    static int smem_set = 0;
    if (!smem_set) {
        cudaFuncSetAttribute(gemm_tf32<0>, cudaFuncAttributeMaxDynamicSharedMemorySize, DSMEMBF);
        cudaFuncSetAttribute(gemm_tf32<1>, cudaFuncAttributeMaxDynamicSharedMemorySize, DSMEMBF);
        cudaFuncSetAttribute(gemm_tf32<2>, cudaFuncAttributeMaxDynamicSharedMemorySize, DSMEMBF);
        smem_set = 1;
    }

    float *Xt, *Wqt, *Wkt, *Wvt, *Qt, *Kt, *Vt, *S, *Pt;
    cudaGetSymbolAddress((void**)&Xt, g_Xt);
    cudaGetSymbolAddress((void**)&Wqt, g_Wqt);
    cudaGetSymbolAddress((void**)&Wkt, g_Wkt);
    cudaGetSymbolAddress((void**)&Wvt, g_Wvt);
    cudaGetSymbolAddress((void**)&Qt, g_Qt);
    cudaGetSymbolAddress((void**)&Kt, g_Kt);
    cudaGetSymbolAddress((void**)&Vt, g_Vt);
    cudaGetSymbolAddress((void**)&S, g_S);
    cudaGetSymbolAddress((void**)&Pt, g_Pt);

    const size_t nX = (size_t)MS * Dv;

    // 1) round X to tf32; transpose+round weights (W^T -> [N,K] K-major)
    round_kernel<<<(unsigned)(nX / 1024), 256>>>(x, Xt, nX);
    {
        dim3 b(32, 8), g(DQ / 32, Dv / 32, 1);
        roundT_kernel<<<g, b>>>(wq, Wqt, Dv, DQ);
        roundT_kernel<<<g, b>>>(wk, Wkt, Dv, DQ);
        roundT_kernel<<<g, b>>>(wv, Wvt, Dv, DQ);
    }

    // 2) QKV projections (tf32), emit tf32-rounded outputs
    {
        dim3 grid(DQ / TILE, MS / TILE, 1);
        gemm_tf32<1><<<grid, GEMM_THREADS, DSMEMBF>>>(Xt, Wqt, Qt, DQ, Dv, 1.0f, 0, 0, 0);
        gemm_tf32<1><<<grid, GEMM_THREADS, DSMEMBF>>>(Xt, Wkt, Kt, DQ, Dv, 1.0f, 0, 0, 0);
        gemm_tf32<2><<<grid, GEMM_THREADS, DSMEMBF>>>(Xt, Wvt, Vt, DQ, Dv, 1.0f, 0, 0, 0);
    }

    // 3) scores S = Q K^T / 32 (tf32, batched)
    {
        dim3 grid(Sv / TILE, Sv / TILE, Bv);
        gemm_tf32<0><<<grid, GEMM_THREADS, DSMEMBF>>>(
            Qt, Kt, S, Sv, DQ, 0.03125f,
            (size_t)Sv * DQ, (size_t)Sv * DQ, (size_t)Sv * Sv);
    }

    // 4) softmax -> P (tf32-rounded fp32)
    softmax_tf32_kernel<<<Bv * Sv, 256>>>(S, Pt);

    // 5) O = P V (tf32; P:[S,S], V^T:[DQ,S] K-major)
    {
        dim3 grid(DQ / TILE, Sv / TILE, Bv);
        gemm_tf32<0><<<grid, GEMM_THREADS, DSMEMBF>>>(
            Pt, Vt, out, DQ, Sv, 1.0f,
            (size_t)Sv * Sv, (size_t)DQ * Sv, (size_t)Sv * DQ);
    }
}